// round 1
// baseline (speedup 1.0000x reference)
#include <cuda_runtime.h>
#include <math.h>

#define ALPHA_C 0.5f
#define EPS_C   0.01f
#define NBd 4096
#define NXd 512
#define NYd 256
#define NUd 256
#define NQd 256
#define NXQ 768

// ---------------- device scratch (static, no allocation) ----------------
__device__ float g_H[NXQ * NXQ];       // X X^T + eps I
__device__ float g_Pi[NXd * NXd];      // P_inv P_inv^T
__device__ float g_MmT[NXd * NXd];     // MmT[j][n] = -0.5 H[n][j] - S[n][j] + S[j][n]
__device__ float g_NmT[NQd * NXd];     // NmT[j][n] = -(H[n][NX+j] + U[n][j])
__device__ float g_laminv[NQd];        // 1/lam[k] = 2 / H22diag[k]
__device__ float g_D11T[NQd * NQd];    // D11T[j][k] = D11[k][j]
__device__ float g_C1[NQd * NXd];      // C1[k][i] = U[i][k]/lam[k]
__device__ float g_Amat[NXd * NXd];    // A
__device__ float g_B1mat[NXd * NQd];   // B1
__device__ float g_a[NBd * NQd];       // pre-activation a
__device__ float g_w[NBd * NQd];       // solved w

// ---------------- generic multi-segment NT GEMM ----------------
// C[M][N] = sum_seg Aseg[M][Ks] @ Bseg[N][Ks]^T  (+ diagAdd on i==j)
// M % 128 == 0, N % 64 == 0, K % 16 == 0 (all shapes here satisfy this)
#define GBM 128
#define GBN 64
#define GBK 16
#define GTM 8
#define GTN 4

__global__ __launch_bounds__(256) void gemm_nt(
    const float* __restrict__ A0, const float* __restrict__ B0, int K0,
    const float* __restrict__ A1, const float* __restrict__ B1p, int K1,
    const float* __restrict__ A2, const float* __restrict__ B2p, int K2,
    float* __restrict__ C, int M, int N, float diagAdd)
{
    __shared__ float As[GBK][GBM];
    __shared__ float Bs[GBK][GBN];

    const int tid = threadIdx.x;
    const int ty  = tid >> 4;        // 0..15  (row group)
    const int tx  = tid & 15;        // 0..15  (col group)
    const int bm  = blockIdx.y * GBM;
    const int bn  = blockIdx.x * GBN;

    const int a_row = tid >> 2;          // 0..63
    const int a_c4  = (tid & 3) * 4;     // 0,4,8,12

    float acc[GTM][GTN];
#pragma unroll
    for (int i = 0; i < GTM; ++i)
#pragma unroll
        for (int j = 0; j < GTN; ++j) acc[i][j] = 0.f;

    for (int seg = 0; seg < 3; ++seg) {
        const float* Ag; const float* Bg; int K;
        if (seg == 0)      { Ag = A0; Bg = B0;  K = K0; }
        else if (seg == 1) { Ag = A1; Bg = B1p; K = K1; }
        else               { Ag = A2; Bg = B2p; K = K2; }
        if (Ag == nullptr || K <= 0) continue;

        for (int k0 = 0; k0 < K; k0 += GBK) {
            // prefetch into registers before sync
            float4 va0 = *(const float4*)(Ag + (bm + a_row)       * K + k0 + a_c4);
            float4 va1 = *(const float4*)(Ag + (bm + a_row + 64)  * K + k0 + a_c4);
            float4 vb  = *(const float4*)(Bg + (bn + a_row)       * K + k0 + a_c4);

            __syncthreads();   // previous compute done before overwriting smem
            As[a_c4 + 0][a_row] = va0.x;
            As[a_c4 + 1][a_row] = va0.y;
            As[a_c4 + 2][a_row] = va0.z;
            As[a_c4 + 3][a_row] = va0.w;
            As[a_c4 + 0][a_row + 64] = va1.x;
            As[a_c4 + 1][a_row + 64] = va1.y;
            As[a_c4 + 2][a_row + 64] = va1.z;
            As[a_c4 + 3][a_row + 64] = va1.w;
            Bs[a_c4 + 0][a_row] = vb.x;
            Bs[a_c4 + 1][a_row] = vb.y;
            Bs[a_c4 + 2][a_row] = vb.z;
            Bs[a_c4 + 3][a_row] = vb.w;
            __syncthreads();

#pragma unroll
            for (int kk = 0; kk < GBK; ++kk) {
                float4 a0 = *(const float4*)&As[kk][ty * GTM];
                float4 a1 = *(const float4*)&As[kk][ty * GTM + 4];
                float4 bb = *(const float4*)&Bs[kk][tx * GTN];
                float ar[GTM] = {a0.x, a0.y, a0.z, a0.w, a1.x, a1.y, a1.z, a1.w};
                float br[GTN] = {bb.x, bb.y, bb.z, bb.w};
#pragma unroll
                for (int i = 0; i < GTM; ++i)
#pragma unroll
                    for (int j = 0; j < GTN; ++j)
                        acc[i][j] = fmaf(ar[i], br[j], acc[i][j]);
            }
        }
    }

    const int gn0 = bn + tx * GTN;
#pragma unroll
    for (int i = 0; i < GTM; ++i) {
        int gm = bm + ty * GTM + i;
        float4 v = make_float4(acc[i][0], acc[i][1], acc[i][2], acc[i][3]);
        if (diagAdd != 0.f) {
            if (gm == gn0 + 0) v.x += diagAdd;
            if (gm == gn0 + 1) v.y += diagAdd;
            if (gm == gn0 + 2) v.z += diagAdd;
            if (gm == gn0 + 3) v.w += diagAdd;
        }
        *(float4*)(C + gm * N + gn0) = v;
    }
}

// ---------------- frame elementwise builders ----------------
__global__ void build_MN_kernel(const float* __restrict__ S, const float* __restrict__ U)
{
    int idx = blockIdx.x * blockDim.x + threadIdx.x;
    if (idx < NXd * NXd) {
        int j = idx / NXd, n = idx - j * NXd;
        g_MmT[idx] = -0.5f * g_H[n * NXQ + j] - S[n * NXd + j] + S[j * NXd + n];
    } else {
        int idx2 = idx - NXd * NXd;
        if (idx2 < NQd * NXd) {
            int j = idx2 / NXd, n = idx2 - j * NXd;
            g_NmT[idx2] = -(g_H[n * NXQ + NXd + j] + U[n * NQd + j]);
        }
    }
}

__global__ void build_laminv_kernel()
{
    int k = threadIdx.x;
    if (k < NQd) g_laminv[k] = 2.0f / g_H[(NXd + k) * NXQ + NXd + k];
}

__global__ void build_DC_kernel(const float* __restrict__ U)
{
    int idx = blockIdx.x * blockDim.x + threadIdx.x;
    if (idx < NQd * NQd) {
        int j = idx / NQd, k = idx - j * NQd;
        g_D11T[idx] = (j < k) ? (-g_H[(NXd + k) * NXQ + NXd + j] * g_laminv[k]) : 0.f;
    } else {
        int idx2 = idx - NQd * NQd;
        if (idx2 < NQd * NXd) {
            int k = idx2 / NXd, i = idx2 - k * NXd;
            g_C1[idx2] = U[i * NQd + k] * g_laminv[k];
        }
    }
}

// ---------------- sequential triangular tanh solve ----------------
// 8 threads per batch row; thread c owns k in [32c, 32c+32) as registers.
// Forward (rank-1) updates: once w_j is known, acc[k] += w_j * D11T[j][k], k > j.
__global__ __launch_bounds__(256, 1) void solve_w_kernel()
{
    __shared__ float s_laminv[NQd];
    const int tid = threadIdx.x;
    s_laminv[tid] = g_laminv[tid];    // blockDim == 256 == NQd
    __syncthreads();

    const int c   = tid & 7;          // thread-in-row
    const int r   = tid >> 3;         // 0..31 rows per CTA
    const int row = blockIdx.x * 32 + r;

    float acc[32];
    float wreg[32];

    const float* arow = g_a + row * NQd + c * 32;
#pragma unroll
    for (int i4 = 0; i4 < 8; ++i4) {
        float4 v = *(const float4*)(arow + 4 * i4);
        acc[4 * i4 + 0] = v.x; acc[4 * i4 + 1] = v.y;
        acc[4 * i4 + 2] = v.z; acc[4 * i4 + 3] = v.w;
    }

    for (int b = 0; b < 8; ++b) {
        const bool after = (c > b);
        const bool owner = (c == b);
#pragma unroll
        for (int jc = 0; jc < 32; ++jc) {
            const int j = (b << 5) + jc;
            // owner computes v; other lanes compute garbage (overwritten by shfl)
            float v  = acc[jc] * s_laminv[j];
            float ex = __expf(v + v);
            float wj = 1.f - __fdividef(2.f, ex + 1.f);   // tanh(v)
            wj = __shfl_sync(0xffffffffu, wj, b, 8);
            if (owner) wreg[jc] = wj;

            const float* drow = g_D11T + j * NQd + c * 32;
#pragma unroll
            for (int i4 = 0; i4 < 8; ++i4) {
                bool anyp = after || (owner && (4 * i4 + 3) > jc);
                float4 d = make_float4(0.f, 0.f, 0.f, 0.f);
                if (anyp) d = *(const float4*)(drow + 4 * i4);
                if (after || (owner && (4 * i4 + 0) > jc)) acc[4 * i4 + 0] = fmaf(wj, d.x, acc[4 * i4 + 0]);
                if (after || (owner && (4 * i4 + 1) > jc)) acc[4 * i4 + 1] = fmaf(wj, d.y, acc[4 * i4 + 1]);
                if (after || (owner && (4 * i4 + 2) > jc)) acc[4 * i4 + 2] = fmaf(wj, d.z, acc[4 * i4 + 2]);
                if (after || (owner && (4 * i4 + 3) > jc)) acc[4 * i4 + 3] = fmaf(wj, d.w, acc[4 * i4 + 3]);
            }
        }
    }

    float* wrow = g_w + row * NQd + c * 32;
#pragma unroll
    for (int i4 = 0; i4 < 8; ++i4) {
        *(float4*)(wrow + 4 * i4) =
            make_float4(wreg[4 * i4 + 0], wreg[4 * i4 + 1], wreg[4 * i4 + 2], wreg[4 * i4 + 3]);
    }
}

// ---------------- launch ----------------
extern "C" void kernel_launch(void* const* d_in, const int* in_sizes, int n_in,
                              void* d_out, int out_size)
{
    const float* u_in  = (const float*)d_in[0];   // (4096, 256)
    const float* x_in  = (const float*)d_in[1];   // (4096, 512)
    const float* X_in  = (const float*)d_in[2];   // (768, 768)
    const float* S_in  = (const float*)d_in[3];   // (512, 512)
    const float* Pv_in = (const float*)d_in[4];   // (512, 512)
    const float* U_in  = (const float*)d_in[5];   // (512, 256)
    const float* D12   = (const float*)d_in[6];   // (256, 256)
    const float* B2    = (const float*)d_in[7];   // (512, 256)
    const float* C2    = (const float*)d_in[8];   // (256, 512)
    const float* D21   = (const float*)d_in[9];   // (256, 256)
    const float* D22   = (const float*)d_in[10];  // (256, 256)

    float* out = (float*)d_out;
    float* dx  = out;                       // (4096, 512)
    float* y   = out + (size_t)NBd * NXd;   // (4096, 256)

    float *H, *Pi, *MmT, *NmT, *D11T, *C1, *Amat, *B1mat, *a, *w;
    cudaGetSymbolAddress((void**)&H,     g_H);
    cudaGetSymbolAddress((void**)&Pi,    g_Pi);
    cudaGetSymbolAddress((void**)&MmT,   g_MmT);
    cudaGetSymbolAddress((void**)&NmT,   g_NmT);
    cudaGetSymbolAddress((void**)&D11T,  g_D11T);
    cudaGetSymbolAddress((void**)&C1,    g_C1);
    cudaGetSymbolAddress((void**)&Amat,  g_Amat);
    cudaGetSymbolAddress((void**)&B1mat, g_B1mat);
    cudaGetSymbolAddress((void**)&a,     g_a);
    cudaGetSymbolAddress((void**)&w,     g_w);

    dim3 blk(256);

    // H = X X^T + eps I   (768x768, K=768)
    gemm_nt<<<dim3(NXQ / GBN, NXQ / GBM), blk>>>(
        X_in, X_in, NXQ, nullptr, nullptr, 0, nullptr, nullptr, 0,
        H, NXQ, NXQ, EPS_C);

    // Pi = P_inv P_inv^T  (512x512, K=512)
    gemm_nt<<<dim3(NXd / GBN, NXd / GBM), blk>>>(
        Pv_in, Pv_in, NXd, nullptr, nullptr, 0, nullptr, nullptr, 0,
        Pi, NXd, NXd, 0.f);

    // MmT, NmT
    build_MN_kernel<<<(NXd * NXd + NQd * NXd + 255) / 256, 256>>>(S_in, U_in);

    // laminv, then D11T & C1
    build_laminv_kernel<<<1, 256>>>();
    build_DC_kernel<<<(NQd * NQd + NQd * NXd + 255) / 256, 256>>>(U_in);

    // A = Pi @ M - alpha I   (512x512, K=512)
    gemm_nt<<<dim3(NXd / GBN, NXd / GBM), blk>>>(
        Pi, MmT, NXd, nullptr, nullptr, 0, nullptr, nullptr, 0,
        Amat, NXd, NXd, -ALPHA_C);

    // B1 = Pi @ N            (512x256, K=512)
    gemm_nt<<<dim3(NQd / GBN, NXd / GBM), blk>>>(
        Pi, NmT, NXd, nullptr, nullptr, 0, nullptr, nullptr, 0,
        B1mat, NXd, NQd, 0.f);

    // a = x C1^T + u D12^T   (4096x256)
    gemm_nt<<<dim3(NQd / GBN, NBd / GBM), blk>>>(
        x_in, C1, NXd, u_in, D12, NQd, nullptr, nullptr, 0,
        a, NBd, NQd, 0.f);

    // sequential tanh solve -> w
    solve_w_kernel<<<NBd / 32, 256>>>();

    // dx = x A^T + w B1^T + u B2^T   (4096x512)
    gemm_nt<<<dim3(NXd / GBN, NBd / GBM), blk>>>(
        x_in, Amat, NXd, w, B1mat, NQd, u_in, B2, NQd,
        dx, NBd, NXd, 0.f);

    // y = x C2^T + w D21^T + u D22^T (4096x256)
    gemm_nt<<<dim3(NQd / GBN, NBd / GBM), blk>>>(
        x_in, C2, NXd, w, D21, NQd, u_in, D22, NQd,
        y, NBd, NQd, 0.f);

    (void)in_sizes; (void)n_in; (void)out_size;
}

// round 3
// speedup vs baseline: 1.4622x; 1.4622x over previous
#include <cuda_runtime.h>
#include <cstdint>
#include <math.h>

#define ALPHA_C 0.5f
#define EPS_C   0.01f
#define NBd 4096
#define NXd 512
#define NYd 256
#define NUd 256
#define NQd 256
#define NXQ 768

// ---------------- device scratch (static, no allocation) ----------------
__device__ float g_H[NXQ * NXQ];
__device__ float g_Pi[NXd * NXd];
__device__ float g_MmT[NXd * NXd];
__device__ float g_NmT[NQd * NXd];
__device__ float g_laminv[NQd];
__device__ float g_D11T[NQd * NQd];
__device__ float g_C1[NQd * NXd];
__device__ float g_Amat[NXd * NXd];
__device__ float g_B1mat[NXd * NQd];
__device__ float g_a[NBd * NQd];
__device__ float g_w[NBd * NQd];

// ---------------- mma.sync tf32 NT GEMM ----------------
// C[M][N] = sum_seg Aseg[M][Ks] @ Bseg[N][Ks]^T  (+ diagAdd on i==j)
// CTA tile 128x128, BK=32. 8 warps, each 64x32 (4x4 atoms of m16n8k8).
// M%128==0, N%128==0, K%32==0 for all shapes used here.
#define TBM 128
#define TBN 128
#define TBK 32
#define SROW 36          // smem row stride in floats (16B-aligned, conflict-free frags)

__device__ __forceinline__ uint32_t f2tf32(float f) {
    uint32_t r;
    asm("cvt.rna.tf32.f32 %0, %1;" : "=r"(r) : "f"(f));
    return r;
}

__device__ __forceinline__ void mma_tf32(float c[4], const uint32_t a[4], const uint32_t b[2]) {
    asm volatile(
        "mma.sync.aligned.m16n8k8.row.col.f32.tf32.tf32.f32 "
        "{%0,%1,%2,%3}, {%4,%5,%6,%7}, {%8,%9}, {%0,%1,%2,%3};"
        : "+f"(c[0]), "+f"(c[1]), "+f"(c[2]), "+f"(c[3])
        : "r"(a[0]), "r"(a[1]), "r"(a[2]), "r"(a[3]), "r"(b[0]), "r"(b[1]));
}

__global__ __launch_bounds__(256) void gemm_tc(
    const float* __restrict__ A0, const float* __restrict__ B0, int K0,
    const float* __restrict__ A1, const float* __restrict__ B1p, int K1,
    const float* __restrict__ A2, const float* __restrict__ B2p, int K2,
    float* __restrict__ C, int N, float diagAdd)
{
    __shared__ uint32_t sA[TBM * SROW];
    __shared__ uint32_t sB[TBN * SROW];

    const int tid = threadIdx.x;
    const int wid = tid >> 5;
    const int lane = tid & 31;
    const int g   = lane >> 2;     // groupID 0..7
    const int tig = lane & 3;      // thread-in-group 0..3

    const int bm = blockIdx.y * TBM;
    const int bn = blockIdx.x * TBN;
    const int wm = (wid & 1) * 64;       // warp M offset in tile
    const int wn = (wid >> 1) * 32;      // warp N offset in tile

    // loader mapping: 2 threads per row, 16 floats each
    const int lrow = tid >> 1;           // 0..127
    const int lcol = (tid & 1) * 16;     // 0 or 16

    float acc[4][4][4];
#pragma unroll
    for (int i = 0; i < 4; ++i)
#pragma unroll
        for (int j = 0; j < 4; ++j)
#pragma unroll
            for (int q = 0; q < 4; ++q) acc[i][j][q] = 0.f;

    for (int seg = 0; seg < 3; ++seg) {
        const float* Ag; const float* Bg; int K;
        if (seg == 0)      { Ag = A0; Bg = B0;  K = K0; }
        else if (seg == 1) { Ag = A1; Bg = B1p; K = K1; }
        else               { Ag = A2; Bg = B2p; K = K2; }
        if (Ag == nullptr || K <= 0) continue;

        for (int k0 = 0; k0 < K; k0 += TBK) {
            // ---- gmem -> reg ----
            float4 ra[4], rb[4];
            const float* ap = Ag + (size_t)(bm + lrow) * K + k0 + lcol;
            const float* bp = Bg + (size_t)(bn + lrow) * K + k0 + lcol;
#pragma unroll
            for (int q = 0; q < 4; ++q) { ra[q] = *(const float4*)(ap + 4 * q); }
#pragma unroll
            for (int q = 0; q < 4; ++q) { rb[q] = *(const float4*)(bp + 4 * q); }

            __syncthreads();   // previous compute done
            // ---- convert to tf32 + store to smem ----
#pragma unroll
            for (int q = 0; q < 4; ++q) {
                uint4 qa = make_uint4(f2tf32(ra[q].x), f2tf32(ra[q].y), f2tf32(ra[q].z), f2tf32(ra[q].w));
                uint4 qb = make_uint4(f2tf32(rb[q].x), f2tf32(rb[q].y), f2tf32(rb[q].z), f2tf32(rb[q].w));
                *(uint4*)&sA[lrow * SROW + lcol + 4 * q] = qa;
                *(uint4*)&sB[lrow * SROW + lcol + 4 * q] = qb;
            }
            __syncthreads();

            // ---- compute: 4 k-steps of k8 ----
#pragma unroll
            for (int k8 = 0; k8 < TBK; k8 += 8) {
                uint32_t afr[4][4];
                uint32_t bfr[4][2];
#pragma unroll
                for (int im = 0; im < 4; ++im) {
                    int base = (wm + 16 * im + g) * SROW + k8 + tig;
                    afr[im][0] = sA[base];
                    afr[im][1] = sA[base + 8 * SROW];
                    afr[im][2] = sA[base + 4];
                    afr[im][3] = sA[base + 8 * SROW + 4];
                }
#pragma unroll
                for (int in_ = 0; in_ < 4; ++in_) {
                    int base = (wn + 8 * in_ + g) * SROW + k8 + tig;
                    bfr[in_][0] = sB[base];
                    bfr[in_][1] = sB[base + 4];
                }
#pragma unroll
                for (int im = 0; im < 4; ++im)
#pragma unroll
                    for (int in_ = 0; in_ < 4; ++in_)
                        mma_tf32(acc[im][in_], afr[im], bfr[in_]);
            }
        }
    }

    // ---- epilogue ----
#pragma unroll
    for (int im = 0; im < 4; ++im) {
#pragma unroll
        for (int in_ = 0; in_ < 4; ++in_) {
            int row0 = bm + wm + 16 * im + g;
            int col0 = bn + wn + 8 * in_ + 2 * tig;
            float c0 = acc[im][in_][0], c1 = acc[im][in_][1];
            float c2 = acc[im][in_][2], c3 = acc[im][in_][3];
            if (diagAdd != 0.f) {
                if (row0 == col0)         c0 += diagAdd;
                if (row0 == col0 + 1)     c1 += diagAdd;
                if (row0 + 8 == col0)     c2 += diagAdd;
                if (row0 + 8 == col0 + 1) c3 += diagAdd;
            }
            *(float2*)(C + (size_t)row0 * N + col0)       = make_float2(c0, c1);
            *(float2*)(C + (size_t)(row0 + 8) * N + col0) = make_float2(c2, c3);
        }
    }
}

// ---------------- frame elementwise builders ----------------
__global__ void build_MN_kernel(const float* __restrict__ S, const float* __restrict__ U)
{
    int idx = blockIdx.x * blockDim.x + threadIdx.x;
    if (idx < NXd * NXd) {
        int j = idx / NXd, n = idx - j * NXd;
        g_MmT[idx] = -0.5f * g_H[n * NXQ + j] - S[n * NXd + j] + S[j * NXd + n];
    } else {
        int idx2 = idx - NXd * NXd;
        if (idx2 < NQd * NXd) {
            int j = idx2 / NXd, n = idx2 - j * NXd;
            g_NmT[idx2] = -(g_H[n * NXQ + NXd + j] + U[n * NQd + j]);
        }
    }
}

__global__ void build_laminv_kernel()
{
    int k = threadIdx.x;
    if (k < NQd) g_laminv[k] = 2.0f / g_H[(NXd + k) * NXQ + NXd + k];
}

__global__ void build_DC_kernel(const float* __restrict__ U)
{
    int idx = blockIdx.x * blockDim.x + threadIdx.x;
    if (idx < NQd * NQd) {
        int j = idx / NQd, k = idx - j * NQd;
        g_D11T[idx] = (j < k) ? (-g_H[(NXd + k) * NXQ + NXd + j] * g_laminv[k]) : 0.f;
    } else {
        int idx2 = idx - NQd * NQd;
        if (idx2 < NQd * NXd) {
            int k = idx2 / NXd, i = idx2 - k * NXd;
            g_C1[idx2] = U[i * NQd + k] * g_laminv[k];
        }
    }
}

// ---------------- sequential triangular tanh solve ----------------
__global__ __launch_bounds__(256, 1) void solve_w_kernel()
{
    __shared__ float s_laminv[NQd];
    const int tid = threadIdx.x;
    s_laminv[tid] = g_laminv[tid];
    __syncthreads();

    const int c   = tid & 7;
    const int r   = tid >> 3;
    const int row = blockIdx.x * 32 + r;

    float acc[32];
    float wreg[32];

    const float* arow = g_a + row * NQd + c * 32;
#pragma unroll
    for (int i4 = 0; i4 < 8; ++i4) {
        float4 v = *(const float4*)(arow + 4 * i4);
        acc[4 * i4 + 0] = v.x; acc[4 * i4 + 1] = v.y;
        acc[4 * i4 + 2] = v.z; acc[4 * i4 + 3] = v.w;
    }

    for (int b = 0; b < 8; ++b) {
        const bool after = (c > b);
        const bool owner = (c == b);
#pragma unroll
        for (int jc = 0; jc < 32; ++jc) {
            const int j = (b << 5) + jc;
            float v  = acc[jc] * s_laminv[j];
            float ex = __expf(v + v);
            float wj = 1.f - __fdividef(2.f, ex + 1.f);
            wj = __shfl_sync(0xffffffffu, wj, b, 8);
            if (owner) wreg[jc] = wj;

            const float* drow = g_D11T + j * NQd + c * 32;
#pragma unroll
            for (int i4 = 0; i4 < 8; ++i4) {
                bool anyp = after || (owner && (4 * i4 + 3) > jc);
                float4 d = make_float4(0.f, 0.f, 0.f, 0.f);
                if (anyp) d = *(const float4*)(drow + 4 * i4);
                if (after || (owner && (4 * i4 + 0) > jc)) acc[4 * i4 + 0] = fmaf(wj, d.x, acc[4 * i4 + 0]);
                if (after || (owner && (4 * i4 + 1) > jc)) acc[4 * i4 + 1] = fmaf(wj, d.y, acc[4 * i4 + 1]);
                if (after || (owner && (4 * i4 + 2) > jc)) acc[4 * i4 + 2] = fmaf(wj, d.z, acc[4 * i4 + 2]);
                if (after || (owner && (4 * i4 + 3) > jc)) acc[4 * i4 + 3] = fmaf(wj, d.w, acc[4 * i4 + 3]);
            }
        }
    }

    float* wrow = g_w + row * NQd + c * 32;
#pragma unroll
    for (int i4 = 0; i4 < 8; ++i4) {
        *(float4*)(wrow + 4 * i4) =
            make_float4(wreg[4 * i4 + 0], wreg[4 * i4 + 1], wreg[4 * i4 + 2], wreg[4 * i4 + 3]);
    }
}

// ---------------- launch ----------------
extern "C" void kernel_launch(void* const* d_in, const int* in_sizes, int n_in,
                              void* d_out, int out_size)
{
    const float* u_in  = (const float*)d_in[0];
    const float* x_in  = (const float*)d_in[1];
    const float* X_in  = (const float*)d_in[2];
    const float* S_in  = (const float*)d_in[3];
    const float* Pv_in = (const float*)d_in[4];
    const float* U_in  = (const float*)d_in[5];
    const float* D12   = (const float*)d_in[6];
    const float* B2    = (const float*)d_in[7];
    const float* C2    = (const float*)d_in[8];
    const float* D21   = (const float*)d_in[9];
    const float* D22   = (const float*)d_in[10];

    float* out = (float*)d_out;
    float* dx  = out;
    float* y   = out + (size_t)NBd * NXd;

    float *H, *Pi, *MmT, *NmT, *D11T, *C1, *Amat, *B1mat, *a, *w;
    cudaGetSymbolAddress((void**)&H,     g_H);
    cudaGetSymbolAddress((void**)&Pi,    g_Pi);
    cudaGetSymbolAddress((void**)&MmT,   g_MmT);
    cudaGetSymbolAddress((void**)&NmT,   g_NmT);
    cudaGetSymbolAddress((void**)&D11T,  g_D11T);
    cudaGetSymbolAddress((void**)&C1,    g_C1);
    cudaGetSymbolAddress((void**)&Amat,  g_Amat);
    cudaGetSymbolAddress((void**)&B1mat, g_B1mat);
    cudaGetSymbolAddress((void**)&a,     g_a);
    cudaGetSymbolAddress((void**)&w,     g_w);

    dim3 blk(256);

    // H = X X^T + eps I   (768x768, K=768)
    gemm_tc<<<dim3(NXQ / TBN, NXQ / TBM), blk>>>(
        X_in, X_in, NXQ, nullptr, nullptr, 0, nullptr, nullptr, 0,
        H, NXQ, EPS_C);

    // Pi = P_inv P_inv^T  (512x512, K=512)
    gemm_tc<<<dim3(NXd / TBN, NXd / TBM), blk>>>(
        Pv_in, Pv_in, NXd, nullptr, nullptr, 0, nullptr, nullptr, 0,
        Pi, NXd, 0.f);

    build_MN_kernel<<<(NXd * NXd + NQd * NXd + 255) / 256, 256>>>(S_in, U_in);
    build_laminv_kernel<<<1, 256>>>();
    build_DC_kernel<<<(NQd * NQd + NQd * NXd + 255) / 256, 256>>>(U_in);

    // A = Pi @ M - alpha I   (512x512, K=512)
    gemm_tc<<<dim3(NXd / TBN, NXd / TBM), blk>>>(
        Pi, MmT, NXd, nullptr, nullptr, 0, nullptr, nullptr, 0,
        Amat, NXd, -ALPHA_C);

    // B1 = Pi @ N            (512x256, K=512)
    gemm_tc<<<dim3(NQd / TBN, NXd / TBM), blk>>>(
        Pi, NmT, NXd, nullptr, nullptr, 0, nullptr, nullptr, 0,
        B1mat, NQd, 0.f);

    // a = x C1^T + u D12^T   (4096x256)
    gemm_tc<<<dim3(NQd / TBN, NBd / TBM), blk>>>(
        x_in, C1, NXd, u_in, D12, NQd, nullptr, nullptr, 0,
        a, NQd, 0.f);

    // sequential tanh solve -> w
    solve_w_kernel<<<NBd / 32, 256>>>();

    // dx = x A^T + w B1^T + u B2^T   (4096x512)
    gemm_tc<<<dim3(NXd / TBN, NBd / TBM), blk>>>(
        x_in, Amat, NXd, w, B1mat, NQd, u_in, B2, NQd,
        dx, NXd, 0.f);

    // y = x C2^T + w D21^T + u D22^T (4096x256)
    gemm_tc<<<dim3(NQd / TBN, NBd / TBM), blk>>>(
        x_in, C2, NXd, w, D21, NQd, u_in, D22, NQd,
        y, NQd, 0.f);

    (void)in_sizes; (void)n_in; (void)out_size;
}

// round 4
// speedup vs baseline: 1.7100x; 1.1695x over previous
#include <cuda_runtime.h>
#include <cstdint>
#include <math.h>

#define ALPHA_C 0.5f
#define EPS_C   0.01f
#define NBd 4096
#define NXd 512
#define NYd 256
#define NUd 256
#define NQd 256
#define NXQ 768

#define TBK 32
#define SROW 36

// ---------------- device scratch ----------------
__device__ float g_H[NXQ * NXQ];
__device__ float g_Pi[NXd * NXd];
__device__ float g_MmT[NXd * NXd];
__device__ float g_NmT[NQd * NXd];
__device__ float g_laminv[NQd];
__device__ float g_D11T[NQd * NQd];
__device__ float g_C1[NQd * NXd];
__device__ float g_BigB0[(NXd + NYd) * NXd];   // [A ; C2]   768 x 512
__device__ float g_BigB1[(NXd + NYd) * NQd];   // [B1 ; D21] 768 x 256
__device__ float g_BigB2[(NXd + NYd) * NUd];   // [B2 ; D22] 768 x 256
__device__ float g_a[NBd * NQd];
__device__ float g_w[NBd * NQd];

__device__ __forceinline__ uint32_t f2tf32(float f) {
    uint32_t r;
    asm("cvt.rna.tf32.f32 %0, %1;" : "=r"(r) : "f"(f));
    return r;
}
__device__ __forceinline__ void mma_tf32(float c[4], const uint32_t a[4], const uint32_t b[2]) {
    asm volatile(
        "mma.sync.aligned.m16n8k8.row.col.f32.tf32.tf32.f32 "
        "{%0,%1,%2,%3}, {%4,%5,%6,%7}, {%8,%9}, {%0,%1,%2,%3};"
        : "+f"(c[0]), "+f"(c[1]), "+f"(c[2]), "+f"(c[3])
        : "r"(a[0]), "r"(a[1]), "r"(a[2]), "r"(a[3]), "r"(b[0]), "r"(b[1]));
}

// ---------------- pipelined mma.sync tf32 NT GEMM (template) ----------------
// C = sum_seg Aseg[M][Ks] @ Bseg[N][Ks]^T  (+ diagAdd on i==j)
// Square CTA tile TBM x TBM; double-buffered smem; LDG(k+1) overlaps MMA(k).
// Output split: global col < NSPLIT -> C0 (stride N0) else C1 (stride N1).
template<int TBM_, int WM_, int WN_>
__global__ void __launch_bounds__(WM_ * WN_ * 32) gemm_tc_t(
    const float* __restrict__ A0, const float* __restrict__ B0, int K0,
    const float* __restrict__ A1, const float* __restrict__ B1p, int K1,
    const float* __restrict__ A2, const float* __restrict__ B2p, int K2,
    float* __restrict__ C0, int N0, float* __restrict__ C1, int N1, int NSPLIT,
    float diagAdd)
{
    constexpr int THREADS = WM_ * WN_ * 32;
    constexpr int IM = TBM_ / WM_ / 16;
    constexpr int IN = TBM_ / WN_ / 8;
    constexpr int SZ = TBM_ * SROW;
    static_assert(THREADS == 2 * TBM_, "loader mapping needs threads == 2*TBM");

    extern __shared__ uint32_t smem[];
    uint32_t* sA = smem;            // [2][SZ]
    uint32_t* sB = smem + 2 * SZ;   // [2][SZ]

    const int tid  = threadIdx.x;
    const int wid  = tid >> 5;
    const int lane = tid & 31;
    const int g    = lane >> 2;
    const int tig  = lane & 3;
    const int bm = blockIdx.y * TBM_;
    const int bn = blockIdx.x * TBM_;
    const int wm = (wid % WM_) * (TBM_ / WM_);
    const int wn = (wid / WM_) * (TBM_ / WN_);
    const int lrow = tid >> 1;
    const int lcol = (tid & 1) * 16;

    float acc[IM][IN][4];
#pragma unroll
    for (int i = 0; i < IM; ++i)
#pragma unroll
        for (int j = 0; j < IN; ++j)
#pragma unroll
            for (int q = 0; q < 4; ++q) acc[i][j][q] = 0.f;

    const int nch0 = K0 / TBK, nch1 = K1 / TBK, nch2 = K2 / TBK;
    const int nch = nch0 + nch1 + nch2;

    float4 ra[4], rb[4];
    const float* Ap = A0; const float* Bp = B0; int Kk = K0; int k0 = 0;

    auto getc = [&](int c) {
        if (c < nch0)              { Ap = A0; Bp = B0;  Kk = K0; k0 = c * TBK; }
        else if (c < nch0 + nch1)  { Ap = A1; Bp = B1p; Kk = K1; k0 = (c - nch0) * TBK; }
        else                       { Ap = A2; Bp = B2p; Kk = K2; k0 = (c - nch0 - nch1) * TBK; }
    };
    auto ldg = [&]() {
        const float* ap = Ap + (size_t)(bm + lrow) * Kk + k0 + lcol;
        const float* bp = Bp + (size_t)(bn + lrow) * Kk + k0 + lcol;
#pragma unroll
        for (int q = 0; q < 4; ++q) { ra[q] = *(const float4*)(ap + 4 * q); }
#pragma unroll
        for (int q = 0; q < 4; ++q) { rb[q] = *(const float4*)(bp + 4 * q); }
    };
    auto sts = [&](int b) {
        uint32_t* dA = sA + b * SZ + lrow * SROW + lcol;
        uint32_t* dB = sB + b * SZ + lrow * SROW + lcol;
#pragma unroll
        for (int q = 0; q < 4; ++q) {
            *(uint4*)(dA + 4 * q) = make_uint4(f2tf32(ra[q].x), f2tf32(ra[q].y),
                                               f2tf32(ra[q].z), f2tf32(ra[q].w));
            *(uint4*)(dB + 4 * q) = make_uint4(f2tf32(rb[q].x), f2tf32(rb[q].y),
                                               f2tf32(rb[q].z), f2tf32(rb[q].w));
        }
    };
    auto comp = [&](int b) {
        const uint32_t* bA = sA + b * SZ;
        const uint32_t* bB = sB + b * SZ;
#pragma unroll
        for (int k8 = 0; k8 < TBK; k8 += 8) {
            uint32_t afr[IM][4];
            uint32_t bfr[IN][2];
#pragma unroll
            for (int im = 0; im < IM; ++im) {
                int base = (wm + 16 * im + g) * SROW + k8 + tig;
                afr[im][0] = bA[base];
                afr[im][1] = bA[base + 8 * SROW];
                afr[im][2] = bA[base + 4];
                afr[im][3] = bA[base + 8 * SROW + 4];
            }
#pragma unroll
            for (int in_ = 0; in_ < IN; ++in_) {
                int base = (wn + 8 * in_ + g) * SROW + k8 + tig;
                bfr[in_][0] = bB[base];
                bfr[in_][1] = bB[base + 4];
            }
#pragma unroll
            for (int im = 0; im < IM; ++im)
#pragma unroll
                for (int in_ = 0; in_ < IN; ++in_)
                    mma_tf32(acc[im][in_], afr[im], bfr[in_]);
        }
    };

    getc(0); ldg(); sts(0);
    __syncthreads();
    for (int c = 0; c < nch; ++c) {
        if (c + 1 < nch) { getc(c + 1); ldg(); }
        comp(c & 1);
        if (c + 1 < nch) { sts((c + 1) & 1); }
        __syncthreads();
    }

    // ---- epilogue with split output ----
#pragma unroll
    for (int im = 0; im < IM; ++im) {
#pragma unroll
        for (int in_ = 0; in_ < IN; ++in_) {
            int row0 = bm + wm + 16 * im + g;
            int col0 = bn + wn + 8 * in_ + 2 * tig;
            float c0 = acc[im][in_][0], c1 = acc[im][in_][1];
            float c2 = acc[im][in_][2], c3 = acc[im][in_][3];
            if (diagAdd != 0.f) {
                if (row0 == col0)         c0 += diagAdd;
                if (row0 == col0 + 1)     c1 += diagAdd;
                if (row0 + 8 == col0)     c2 += diagAdd;
                if (row0 + 8 == col0 + 1) c3 += diagAdd;
            }
            float* base; int st; int cc = col0;
            if (col0 >= NSPLIT) { base = C1; st = N1; cc = col0 - NSPLIT; }
            else                { base = C0; st = N0; }
            *(float2*)(base + (size_t)row0 * st + cc)       = make_float2(c0, c1);
            *(float2*)(base + (size_t)(row0 + 8) * st + cc) = make_float2(c2, c3);
        }
    }
}

// ---------------- frame elementwise builders ----------------
__global__ void build_MN_kernel(const float* __restrict__ S, const float* __restrict__ U)
{
    int idx = blockIdx.x * blockDim.x + threadIdx.x;
    if (idx < NXd * NXd) {
        int j = idx / NXd, n = idx - j * NXd;
        g_MmT[idx] = -0.5f * g_H[n * NXQ + j] - S[n * NXd + j] + S[j * NXd + n];
    } else if (idx < NXd * NXd + NQd * NXd) {
        int idx2 = idx - NXd * NXd;
        int j = idx2 / NXd, n = idx2 - j * NXd;
        g_NmT[idx2] = -(g_H[n * NXQ + NXd + j] + U[n * NQd + j]);
    } else {
        int k = idx - NXd * NXd - NQd * NXd;
        if (k < NQd) g_laminv[k] = 2.0f / g_H[(NXd + k) * NXQ + NXd + k];
    }
}

__global__ void build_DC_kernel(const float* __restrict__ U)
{
    int idx = blockIdx.x * blockDim.x + threadIdx.x;
    if (idx < NQd * NQd) {
        int j = idx / NQd, k = idx - j * NQd;
        g_D11T[idx] = (j < k) ? (-g_H[(NXd + k) * NXQ + NXd + j] * g_laminv[k]) : 0.f;
    } else {
        int idx2 = idx - NQd * NQd;
        if (idx2 < NQd * NXd) {
            int k = idx2 / NXd, i = idx2 - k * NXd;
            g_C1[idx2] = U[i * NQd + k] * g_laminv[k];
        }
    }
}

// ---------------- sequential triangular tanh solve ----------------
__global__ __launch_bounds__(256, 1) void solve_w_kernel()
{
    __shared__ float s_laminv[NQd];
    const int tid = threadIdx.x;
    s_laminv[tid] = g_laminv[tid];
    __syncthreads();

    const int c   = tid & 7;
    const int r   = tid >> 3;
    const int row = blockIdx.x * 32 + r;

    float acc[32];
    float wreg[32];

    const float* arow = g_a + row * NQd + c * 32;
#pragma unroll
    for (int i4 = 0; i4 < 8; ++i4) {
        float4 v = *(const float4*)(arow + 4 * i4);
        acc[4 * i4 + 0] = v.x; acc[4 * i4 + 1] = v.y;
        acc[4 * i4 + 2] = v.z; acc[4 * i4 + 3] = v.w;
    }

    for (int b = 0; b < 8; ++b) {
        const bool after = (c > b);
        const bool owner = (c == b);
#pragma unroll
        for (int jc = 0; jc < 32; ++jc) {
            const int j = (b << 5) + jc;
            float v  = acc[jc] * s_laminv[j];
            float ex = __expf(v + v);
            float wj = 1.f - __fdividef(2.f, ex + 1.f);
            wj = __shfl_sync(0xffffffffu, wj, b, 8);
            if (owner) wreg[jc] = wj;

            const float* drow = g_D11T + j * NQd + c * 32;
#pragma unroll
            for (int i4 = 0; i4 < 8; ++i4) {
                bool anyp = after || (owner && (4 * i4 + 3) > jc);
                float4 d = make_float4(0.f, 0.f, 0.f, 0.f);
                if (anyp) d = *(const float4*)(drow + 4 * i4);
                if (after || (owner && (4 * i4 + 0) > jc)) acc[4 * i4 + 0] = fmaf(wj, d.x, acc[4 * i4 + 0]);
                if (after || (owner && (4 * i4 + 1) > jc)) acc[4 * i4 + 1] = fmaf(wj, d.y, acc[4 * i4 + 1]);
                if (after || (owner && (4 * i4 + 2) > jc)) acc[4 * i4 + 2] = fmaf(wj, d.z, acc[4 * i4 + 2]);
                if (after || (owner && (4 * i4 + 3) > jc)) acc[4 * i4 + 3] = fmaf(wj, d.w, acc[4 * i4 + 3]);
            }
        }
    }

    float* wrow = g_w + row * NQd + c * 32;
#pragma unroll
    for (int i4 = 0; i4 < 8; ++i4) {
        *(float4*)(wrow + 4 * i4) =
            make_float4(wreg[4 * i4 + 0], wreg[4 * i4 + 1], wreg[4 * i4 + 2], wreg[4 * i4 + 3]);
    }
}

// ---------------- launch ----------------
extern "C" void kernel_launch(void* const* d_in, const int* in_sizes, int n_in,
                              void* d_out, int out_size)
{
    const float* u_in  = (const float*)d_in[0];
    const float* x_in  = (const float*)d_in[1];
    const float* X_in  = (const float*)d_in[2];
    const float* S_in  = (const float*)d_in[3];
    const float* Pv_in = (const float*)d_in[4];
    const float* U_in  = (const float*)d_in[5];
    const float* D12   = (const float*)d_in[6];
    const float* B2    = (const float*)d_in[7];
    const float* C2    = (const float*)d_in[8];
    const float* D21   = (const float*)d_in[9];
    const float* D22   = (const float*)d_in[10];

    float* out = (float*)d_out;
    float* dx  = out;
    float* y   = out + (size_t)NBd * NXd;

    float *H, *Pi, *MmT, *NmT, *C1, *BB0, *BB1, *BB2, *a, *w;
    cudaGetSymbolAddress((void**)&H,   g_H);
    cudaGetSymbolAddress((void**)&Pi,  g_Pi);
    cudaGetSymbolAddress((void**)&MmT, g_MmT);
    cudaGetSymbolAddress((void**)&NmT, g_NmT);
    cudaGetSymbolAddress((void**)&C1,  g_C1);
    cudaGetSymbolAddress((void**)&BB0, g_BigB0);
    cudaGetSymbolAddress((void**)&BB1, g_BigB1);
    cudaGetSymbolAddress((void**)&BB2, g_BigB2);
    cudaGetSymbolAddress((void**)&a,   g_a);
    cudaGetSymbolAddress((void**)&w,   g_w);

    auto Big   = gemm_tc_t<128, 2, 4>;   // 256 thr, smem 73728
    auto Small = gemm_tc_t<64, 2, 2>;    // 128 thr, smem 36864
    const int SMEM_BIG   = 4 * 128 * SROW * 4;
    const int SMEM_SMALL = 4 * 64 * SROW * 4;
    cudaFuncSetAttribute(Big,   cudaFuncAttributeMaxDynamicSharedMemorySize, SMEM_BIG);
    cudaFuncSetAttribute(Small, cudaFuncAttributeMaxDynamicSharedMemorySize, SMEM_SMALL);

    const int NOSPLIT = 1 << 30;

    // H = X X^T + eps I   (768x768, K=768) -> 144 CTAs
    Small<<<dim3(NXQ / 64, NXQ / 64), 128, SMEM_SMALL>>>(
        X_in, X_in, NXQ, nullptr, nullptr, 0, nullptr, nullptr, 0,
        H, NXQ, nullptr, 0, NOSPLIT, EPS_C);

    // Pi = P_inv P_inv^T  (512x512) -> 64 CTAs
    Small<<<dim3(NXd / 64, NXd / 64), 128, SMEM_SMALL>>>(
        Pv_in, Pv_in, NXd, nullptr, nullptr, 0, nullptr, nullptr, 0,
        Pi, NXd, nullptr, 0, NOSPLIT, 0.f);

    build_MN_kernel<<<(NXd * NXd + NQd * NXd + NQd + 255) / 256, 256>>>(S_in, U_in);
    build_DC_kernel<<<(NQd * NQd + NQd * NXd + 255) / 256, 256>>>(U_in);

    // A = Pi @ M - alpha I  -> BigB0 rows 0..511
    Small<<<dim3(NXd / 64, NXd / 64), 128, SMEM_SMALL>>>(
        Pi, MmT, NXd, nullptr, nullptr, 0, nullptr, nullptr, 0,
        BB0, NXd, nullptr, 0, NOSPLIT, -ALPHA_C);

    // B1 = Pi @ N  -> BigB1 rows 0..511
    Small<<<dim3(NQd / 64, NXd / 64), 128, SMEM_SMALL>>>(
        Pi, NmT, NXd, nullptr, nullptr, 0, nullptr, nullptr, 0,
        BB1, NQd, nullptr, 0, NOSPLIT, 0.f);

    // concat tails: [A;C2], [B1;D21], [B2;D22]
    cudaMemcpyAsync(BB0 + (size_t)NXd * NXd, C2,  (size_t)NYd * NXd * 4, cudaMemcpyDeviceToDevice);
    cudaMemcpyAsync(BB1 + (size_t)NXd * NQd, D21, (size_t)NYd * NQd * 4, cudaMemcpyDeviceToDevice);
    cudaMemcpyAsync(BB2,                     B2,  (size_t)NXd * NUd * 4, cudaMemcpyDeviceToDevice);
    cudaMemcpyAsync(BB2 + (size_t)NXd * NUd, D22, (size_t)NYd * NUd * 4, cudaMemcpyDeviceToDevice);

    // a = x C1^T + u D12^T  (4096x256) -> 256 CTAs
    Small<<<dim3(NQd / 64, NBd / 64), 128, SMEM_SMALL>>>(
        x_in, C1, NXd, u_in, D12, NQd, nullptr, nullptr, 0,
        a, NQd, nullptr, 0, NOSPLIT, 0.f);

    // sequential tanh solve -> w
    solve_w_kernel<<<NBd / 32, 256>>>();

    // [dx | y] = x [A;C2]^T + w [B1;D21]^T + u [B2;D22]^T  (4096x768) -> 192 CTAs
    Big<<<dim3((NXd + NYd) / 128, NBd / 128), 256, SMEM_BIG>>>(
        x_in, BB0, NXd, w, BB1, NQd, u_in, BB2, NUd,
        dx, NXd, y, NYd, NXd, 0.f);

    (void)in_sizes; (void)n_in; (void)out_size;
}

// round 5
// speedup vs baseline: 1.8205x; 1.0646x over previous
#include <cuda_runtime.h>
#include <cstdint>
#include <math.h>

#define ALPHA_C 0.5f
#define EPS_C   0.01f
#define NBd 4096
#define NXd 512
#define NYd 256
#define NUd 256
#define NQd 256
#define NXQ 768

#define TBK 32
#define SROW 36

// ---------------- device scratch ----------------
__device__ float g_H[NXQ * NXQ];
__device__ float g_Pi[NXd * NXd];
__device__ float g_MmT[NXd * NXd];
__device__ float g_NmT[NQd * NXd];
__device__ float g_laminv[NQd];
__device__ float g_D11T[NQd * NQd];
__device__ float g_C1[NQd * NXd];
__device__ float g_BigB0[(NXd + NYd) * NXd];   // [A ; C2]   768 x 512
__device__ float g_BigB1[(NXd + NYd) * NQd];   // [B1 ; D21] 768 x 256
__device__ float g_BigB2[(NXd + NYd) * NUd];   // [B2 ; D22] 768 x 256
__device__ float g_a[NBd * NQd];
__device__ float g_w[NBd * NQd];

__device__ __forceinline__ uint32_t f2tf32(float f) {
    uint32_t r;
    asm("cvt.rna.tf32.f32 %0, %1;" : "=r"(r) : "f"(f));
    return r;
}
__device__ __forceinline__ void mma_tf32(float c[4], const uint32_t a[4], const uint32_t b[2]) {
    asm volatile(
        "mma.sync.aligned.m16n8k8.row.col.f32.tf32.tf32.f32 "
        "{%0,%1,%2,%3}, {%4,%5,%6,%7}, {%8,%9}, {%0,%1,%2,%3};"
        : "+f"(c[0]), "+f"(c[1]), "+f"(c[2]), "+f"(c[3])
        : "r"(a[0]), "r"(a[1]), "r"(a[2]), "r"(a[3]), "r"(b[0]), "r"(b[1]));
}
__device__ __forceinline__ void ldsm_x4(uint32_t r[4], uint32_t addr) {
    asm volatile("ldmatrix.sync.aligned.m8n8.x4.shared.b16 {%0,%1,%2,%3}, [%4];"
        : "=r"(r[0]), "=r"(r[1]), "=r"(r[2]), "=r"(r[3]) : "r"(addr));
}

// ---------------- pipelined mma.sync tf32 NT GEMM (template) ----------------
// C = sum_seg Aseg[M][Ks] @ Bseg[N][Ks]^T  (+ diagAdd on i==j)
// Square CTA tile TBM x TBM; double-buffered smem; LDG(k+1) overlaps MMA(k).
// Fragments loaded with ldmatrix (tf32 = bit movement over b16 tiles).
template<int TBM_, int WM_, int WN_>
__global__ void __launch_bounds__(WM_ * WN_ * 32) gemm_tc_t(
    const float* __restrict__ A0, const float* __restrict__ B0, int K0,
    const float* __restrict__ A1, const float* __restrict__ B1p, int K1,
    const float* __restrict__ A2, const float* __restrict__ B2p, int K2,
    float* __restrict__ C0, int N0, float* __restrict__ C1, int N1, int NSPLIT,
    float diagAdd)
{
    constexpr int THREADS = WM_ * WN_ * 32;
    constexpr int IM = TBM_ / WM_ / 16;
    constexpr int IN = TBM_ / WN_ / 8;
    constexpr int IP = IN / 2;                 // B ldmatrix pairs
    constexpr int SZ = TBM_ * SROW;
    static_assert(THREADS == 2 * TBM_, "loader mapping needs threads == 2*TBM");
    static_assert((IN & 1) == 0, "IN must be even for paired B ldmatrix");

    extern __shared__ uint32_t smem[];
    uint32_t* sA = smem;            // [2][SZ]
    uint32_t* sB = smem + 2 * SZ;   // [2][SZ]

    const int tid  = threadIdx.x;
    const int wid  = tid >> 5;
    const int lane = tid & 31;
    const int g    = lane >> 2;
    const int tig  = lane & 3;
    const int bm = blockIdx.y * TBM_;
    const int bn = blockIdx.x * TBM_;
    const int wm = (wid % WM_) * (TBM_ / WM_);
    const int wn = (wid / WM_) * (TBM_ / WN_);
    const int lrow = tid >> 1;
    const int lcol = (tid & 1) * 16;

    // ldmatrix per-lane base addresses (bytes, relative to sA/sB buffer start)
    const uint32_t sA_addr = (uint32_t)__cvta_generic_to_shared(sA);
    const uint32_t sB_addr = (uint32_t)__cvta_generic_to_shared(sB);
    uint32_t a_base[IM], b_base[IP];
#pragma unroll
    for (int im = 0; im < IM; ++im)
        a_base[im] = sA_addr +
            (((wm + 16 * im + (lane & 15)) * SROW + 4 * (lane >> 4)) << 2);
#pragma unroll
    for (int p = 0; p < IP; ++p)
        b_base[p] = sB_addr +
            (((wn + 8 * (2 * p + (lane >> 4)) + (lane & 7)) * SROW + 4 * ((lane >> 3) & 1)) << 2);

    float acc[IM][IN][4];
#pragma unroll
    for (int i = 0; i < IM; ++i)
#pragma unroll
        for (int j = 0; j < IN; ++j)
#pragma unroll
            for (int q = 0; q < 4; ++q) acc[i][j][q] = 0.f;

    const int nch0 = K0 / TBK, nch1 = K1 / TBK, nch2 = K2 / TBK;
    const int nch = nch0 + nch1 + nch2;

    float4 ra[4], rb[4];
    const float* Ap = A0; const float* Bp = B0; int Kk = K0; int k0 = 0;

    auto getc = [&](int c) {
        if (c < nch0)              { Ap = A0; Bp = B0;  Kk = K0; k0 = c * TBK; }
        else if (c < nch0 + nch1)  { Ap = A1; Bp = B1p; Kk = K1; k0 = (c - nch0) * TBK; }
        else                       { Ap = A2; Bp = B2p; Kk = K2; k0 = (c - nch0 - nch1) * TBK; }
    };
    auto ldg = [&]() {
        const float* ap = Ap + (size_t)(bm + lrow) * Kk + k0 + lcol;
        const float* bp = Bp + (size_t)(bn + lrow) * Kk + k0 + lcol;
#pragma unroll
        for (int q = 0; q < 4; ++q) { ra[q] = *(const float4*)(ap + 4 * q); }
#pragma unroll
        for (int q = 0; q < 4; ++q) { rb[q] = *(const float4*)(bp + 4 * q); }
    };
    auto sts = [&](int b) {
        uint32_t* dA = sA + b * SZ + lrow * SROW + lcol;
        uint32_t* dB = sB + b * SZ + lrow * SROW + lcol;
#pragma unroll
        for (int q = 0; q < 4; ++q) {
            *(uint4*)(dA + 4 * q) = make_uint4(f2tf32(ra[q].x), f2tf32(ra[q].y),
                                               f2tf32(ra[q].z), f2tf32(ra[q].w));
            *(uint4*)(dB + 4 * q) = make_uint4(f2tf32(rb[q].x), f2tf32(rb[q].y),
                                               f2tf32(rb[q].z), f2tf32(rb[q].w));
        }
    };
    auto comp = [&](int b) {
        const uint32_t boff = (uint32_t)(b * SZ * 4);
#pragma unroll
        for (int k8 = 0; k8 < TBK; k8 += 8) {
            uint32_t afr[IM][4];
            uint32_t bfr[IN][2];
#pragma unroll
            for (int im = 0; im < IM; ++im)
                ldsm_x4(afr[im], a_base[im] + boff + (k8 << 2));
#pragma unroll
            for (int p = 0; p < IP; ++p) {
                uint32_t t[4];
                ldsm_x4(t, b_base[p] + boff + (k8 << 2));
                bfr[2 * p][0] = t[0]; bfr[2 * p][1] = t[1];
                bfr[2 * p + 1][0] = t[2]; bfr[2 * p + 1][1] = t[3];
            }
#pragma unroll
            for (int im = 0; im < IM; ++im)
#pragma unroll
                for (int in_ = 0; in_ < IN; ++in_)
                    mma_tf32(acc[im][in_], afr[im], bfr[in_]);
        }
    };

    getc(0); ldg(); sts(0);
    __syncthreads();
    for (int c = 0; c < nch; ++c) {
        if (c + 1 < nch) { getc(c + 1); ldg(); }
        comp(c & 1);
        if (c + 1 < nch) { sts((c + 1) & 1); }
        __syncthreads();
    }

    // ---- epilogue with split output ----
#pragma unroll
    for (int im = 0; im < IM; ++im) {
#pragma unroll
        for (int in_ = 0; in_ < IN; ++in_) {
            int row0 = bm + wm + 16 * im + g;
            int col0 = bn + wn + 8 * in_ + 2 * tig;
            float c0 = acc[im][in_][0], c1 = acc[im][in_][1];
            float c2 = acc[im][in_][2], c3 = acc[im][in_][3];
            if (diagAdd != 0.f) {
                if (row0 == col0)         c0 += diagAdd;
                if (row0 == col0 + 1)     c1 += diagAdd;
                if (row0 + 8 == col0)     c2 += diagAdd;
                if (row0 + 8 == col0 + 1) c3 += diagAdd;
            }
            float* base; int st; int cc = col0;
            if (col0 >= NSPLIT) { base = C1; st = N1; cc = col0 - NSPLIT; }
            else                { base = C0; st = N0; }
            *(float2*)(base + (size_t)row0 * st + cc)       = make_float2(c0, c1);
            *(float2*)(base + (size_t)(row0 + 8) * st + cc) = make_float2(c2, c3);
        }
    }
}

// ---------------- frame elementwise builders ----------------
__global__ void build_MN_kernel(const float* __restrict__ S, const float* __restrict__ U)
{
    int idx = blockIdx.x * blockDim.x + threadIdx.x;
    if (idx < NXd * NXd) {
        int j = idx / NXd, n = idx - j * NXd;
        g_MmT[idx] = -0.5f * g_H[n * NXQ + j] - S[n * NXd + j] + S[j * NXd + n];
    } else if (idx < NXd * NXd + NQd * NXd) {
        int idx2 = idx - NXd * NXd;
        int j = idx2 / NXd, n = idx2 - j * NXd;
        g_NmT[idx2] = -(g_H[n * NXQ + NXd + j] + U[n * NQd + j]);
    } else {
        int k = idx - NXd * NXd - NQd * NXd;
        if (k < NQd) g_laminv[k] = 2.0f / g_H[(NXd + k) * NXQ + NXd + k];
    }
}

__global__ void build_DC_kernel(const float* __restrict__ U)
{
    int idx = blockIdx.x * blockDim.x + threadIdx.x;
    if (idx < NQd * NQd) {
        int j = idx / NQd, k = idx - j * NQd;
        g_D11T[idx] = (j < k) ? (-g_H[(NXd + k) * NXQ + NXd + j] * g_laminv[k]) : 0.f;
    } else {
        int idx2 = idx - NQd * NQd;
        if (idx2 < NQd * NXd) {
            int k = idx2 / NXd, i = idx2 - k * NXd;
            g_C1[idx2] = U[i * NQd + k] * g_laminv[k];
        }
    }
}

// ---------------- sequential triangular tanh solve ----------------
__global__ __launch_bounds__(256, 1) void solve_w_kernel()
{
    __shared__ float s_laminv[NQd];
    const int tid = threadIdx.x;
    s_laminv[tid] = g_laminv[tid];
    __syncthreads();

    const int c   = tid & 7;
    const int r   = tid >> 3;
    const int row = blockIdx.x * 32 + r;

    float acc[32];
    float wreg[32];

    const float* arow = g_a + row * NQd + c * 32;
#pragma unroll
    for (int i4 = 0; i4 < 8; ++i4) {
        float4 v = *(const float4*)(arow + 4 * i4);
        acc[4 * i4 + 0] = v.x; acc[4 * i4 + 1] = v.y;
        acc[4 * i4 + 2] = v.z; acc[4 * i4 + 3] = v.w;
    }

    for (int b = 0; b < 8; ++b) {
        const bool after = (c > b);
        const bool owner = (c == b);
#pragma unroll
        for (int jc = 0; jc < 32; ++jc) {
            const int j = (b << 5) + jc;
            float v  = acc[jc] * s_laminv[j];
            float ex = __expf(v + v);
            float wj = 1.f - __fdividef(2.f, ex + 1.f);
            wj = __shfl_sync(0xffffffffu, wj, b, 8);
            if (owner) wreg[jc] = wj;

            const float* drow = g_D11T + j * NQd + c * 32;
#pragma unroll
            for (int i4 = 0; i4 < 8; ++i4) {
                bool anyp = after || (owner && (4 * i4 + 3) > jc);
                float4 d = make_float4(0.f, 0.f, 0.f, 0.f);
                if (anyp) d = *(const float4*)(drow + 4 * i4);
                if (after || (owner && (4 * i4 + 0) > jc)) acc[4 * i4 + 0] = fmaf(wj, d.x, acc[4 * i4 + 0]);
                if (after || (owner && (4 * i4 + 1) > jc)) acc[4 * i4 + 1] = fmaf(wj, d.y, acc[4 * i4 + 1]);
                if (after || (owner && (4 * i4 + 2) > jc)) acc[4 * i4 + 2] = fmaf(wj, d.z, acc[4 * i4 + 2]);
                if (after || (owner && (4 * i4 + 3) > jc)) acc[4 * i4 + 3] = fmaf(wj, d.w, acc[4 * i4 + 3]);
            }
        }
    }

    float* wrow = g_w + row * NQd + c * 32;
#pragma unroll
    for (int i4 = 0; i4 < 8; ++i4) {
        *(float4*)(wrow + 4 * i4) =
            make_float4(wreg[4 * i4 + 0], wreg[4 * i4 + 1], wreg[4 * i4 + 2], wreg[4 * i4 + 3]);
    }
}

// ---------------- launch ----------------
extern "C" void kernel_launch(void* const* d_in, const int* in_sizes, int n_in,
                              void* d_out, int out_size)
{
    const float* u_in  = (const float*)d_in[0];
    const float* x_in  = (const float*)d_in[1];
    const float* X_in  = (const float*)d_in[2];
    const float* S_in  = (const float*)d_in[3];
    const float* Pv_in = (const float*)d_in[4];
    const float* U_in  = (const float*)d_in[5];
    const float* D12   = (const float*)d_in[6];
    const float* B2    = (const float*)d_in[7];
    const float* C2    = (const float*)d_in[8];
    const float* D21   = (const float*)d_in[9];
    const float* D22   = (const float*)d_in[10];

    float* out = (float*)d_out;
    float* dx  = out;
    float* y   = out + (size_t)NBd * NXd;

    float *H, *Pi, *MmT, *NmT, *C1, *BB0, *BB1, *BB2, *a, *w;
    cudaGetSymbolAddress((void**)&H,   g_H);
    cudaGetSymbolAddress((void**)&Pi,  g_Pi);
    cudaGetSymbolAddress((void**)&MmT, g_MmT);
    cudaGetSymbolAddress((void**)&NmT, g_NmT);
    cudaGetSymbolAddress((void**)&C1,  g_C1);
    cudaGetSymbolAddress((void**)&BB0, g_BigB0);
    cudaGetSymbolAddress((void**)&BB1, g_BigB1);
    cudaGetSymbolAddress((void**)&BB2, g_BigB2);
    cudaGetSymbolAddress((void**)&a,   g_a);
    cudaGetSymbolAddress((void**)&w,   g_w);

    auto Big   = gemm_tc_t<128, 2, 4>;
    auto Small = gemm_tc_t<64, 2, 2>;
    const int SMEM_BIG   = 4 * 128 * SROW * 4;
    const int SMEM_SMALL = 4 * 64 * SROW * 4;
    cudaFuncSetAttribute(Big,   cudaFuncAttributeMaxDynamicSharedMemorySize, SMEM_BIG);
    cudaFuncSetAttribute(Small, cudaFuncAttributeMaxDynamicSharedMemorySize, SMEM_SMALL);

    const int NOSPLIT = 1 << 30;

    // (1) H = X X^T + eps I   (768x768, K=768)
    Small<<<dim3(NXQ / 64, NXQ / 64), 128, SMEM_SMALL>>>(
        X_in, X_in, NXQ, nullptr, nullptr, 0, nullptr, nullptr, 0,
        H, NXQ, nullptr, 0, NOSPLIT, EPS_C);

    // (2) MmT, NmT, laminv
    build_MN_kernel<<<(NXd * NXd + NQd * NXd + NQd + 255) / 256, 256>>>(S_in, U_in);

    // (3) D11T, C1
    build_DC_kernel<<<(NQd * NQd + NQd * NXd + 255) / 256, 256>>>(U_in);

    // (4) a = x C1^T + u D12^T  (4096x256)  <-- ncu-profiled slot
    Small<<<dim3(NQd / 64, NBd / 64), 128, SMEM_SMALL>>>(
        x_in, C1, NXd, u_in, D12, NQd, nullptr, nullptr, 0,
        a, NQd, nullptr, 0, NOSPLIT, 0.f);

    // (5) Pi = P_inv P_inv^T  (512x512)
    Small<<<dim3(NXd / 64, NXd / 64), 128, SMEM_SMALL>>>(
        Pv_in, Pv_in, NXd, nullptr, nullptr, 0, nullptr, nullptr, 0,
        Pi, NXd, nullptr, 0, NOSPLIT, 0.f);

    // (6) A = Pi @ M - alpha I  -> BigB0 rows 0..511
    Small<<<dim3(NXd / 64, NXd / 64), 128, SMEM_SMALL>>>(
        Pi, MmT, NXd, nullptr, nullptr, 0, nullptr, nullptr, 0,
        BB0, NXd, nullptr, 0, NOSPLIT, -ALPHA_C);

    // (7) B1 = Pi @ N  -> BigB1 rows 0..511
    Small<<<dim3(NQd / 64, NXd / 64), 128, SMEM_SMALL>>>(
        Pi, NmT, NXd, nullptr, nullptr, 0, nullptr, nullptr, 0,
        BB1, NQd, nullptr, 0, NOSPLIT, 0.f);

    // concat tails: [A;C2], [B1;D21], [B2;D22]
    cudaMemcpyAsync(BB0 + (size_t)NXd * NXd, C2,  (size_t)NYd * NXd * 4, cudaMemcpyDeviceToDevice);
    cudaMemcpyAsync(BB1 + (size_t)NXd * NQd, D21, (size_t)NYd * NQd * 4, cudaMemcpyDeviceToDevice);
    cudaMemcpyAsync(BB2,                     B2,  (size_t)NXd * NUd * 4, cudaMemcpyDeviceToDevice);
    cudaMemcpyAsync(BB2 + (size_t)NXd * NUd, D22, (size_t)NYd * NUd * 4, cudaMemcpyDeviceToDevice);

    // (8) sequential tanh solve -> w
    solve_w_kernel<<<NBd / 32, 256>>>();

    // (9) [dx | y] = x [A;C2]^T + w [B1;D21]^T + u [B2;D22]^T  (4096x768)
    Big<<<dim3((NXd + NYd) / 128, NBd / 128), 256, SMEM_BIG>>>(
        x_in, BB0, NXd, w, BB1, NQd, u_in, BB2, NUd,
        dx, NXd, y, NYd, NXd, 0.f);

    (void)in_sizes; (void)n_in; (void)out_size;
}

// round 6
// speedup vs baseline: 1.9877x; 1.0919x over previous
#include <cuda_runtime.h>
#include <cuda_fp16.h>
#include <cstdint>
#include <math.h>

#define ALPHA_C 0.5f
#define EPS_C   0.01f
#define NBd 4096
#define NXd 512
#define NYd 256
#define NUd 256
#define NQd 256
#define NXQ 768

#define TBK 32
#define SROWH 40   // smem row stride in halves (80B): LDSM conflict-free

// ---------------- device scratch ----------------
__device__ float g_H[NXQ * NXQ];
__device__ float g_Pi[NXd * NXd];
__device__ float g_MmT[NXd * NXd];
__device__ float g_NmT[NQd * NXd];
__device__ float g_laminv[NQd];
__device__ float g_D11T[NQd * NQd];
__device__ float g_C1[NQd * NXd];
__device__ float g_BigB0[(NXd + NYd) * NXd];   // [A ; C2]   768 x 512
__device__ float g_BigB1[(NXd + NYd) * NQd];   // [B1 ; D21] 768 x 256
__device__ float g_BigB2[(NXd + NYd) * NUd];   // [B2 ; D22] 768 x 256
__device__ float g_a[NBd * NQd];
__device__ float g_w[NBd * NQd];

__device__ __forceinline__ void mma_f16(float c[4], const uint32_t a[4], const uint32_t b[2]) {
    asm volatile(
        "mma.sync.aligned.m16n8k16.row.col.f32.f16.f16.f32 "
        "{%0,%1,%2,%3}, {%4,%5,%6,%7}, {%8,%9}, {%0,%1,%2,%3};"
        : "+f"(c[0]), "+f"(c[1]), "+f"(c[2]), "+f"(c[3])
        : "r"(a[0]), "r"(a[1]), "r"(a[2]), "r"(a[3]), "r"(b[0]), "r"(b[1]));
}
__device__ __forceinline__ void ldsm_x4(uint32_t r[4], uint32_t addr) {
    asm volatile("ldmatrix.sync.aligned.m8n8.x4.shared.b16 {%0,%1,%2,%3}, [%4];"
        : "=r"(r[0]), "=r"(r[1]), "=r"(r[2]), "=r"(r[3]) : "r"(addr));
}
__device__ __forceinline__ uint32_t h2pack(float lo, float hi) {
    __half2 h = __floats2half2_rn(lo, hi);
    return *(uint32_t*)&h;
}

// ---------------- pipelined fp16 mma.sync NT GEMM (template) ----------------
// C = sum_seg Aseg[M][Ks] @ Bseg[N][Ks]^T  (+ diagAdd on i==j)
// fp32 gmem -> half smem (double-buffered), m16n8k16 fp16 MMA, fp32 accum.
template<int TBM_, int WM_, int WN_>
__global__ void __launch_bounds__(WM_ * WN_ * 32) gemm_tc_t(
    const float* __restrict__ A0, const float* __restrict__ B0, int K0,
    const float* __restrict__ A1, const float* __restrict__ B1p, int K1,
    const float* __restrict__ A2, const float* __restrict__ B2p, int K2,
    float* __restrict__ C0, int N0, float* __restrict__ C1, int N1, int NSPLIT,
    float diagAdd)
{
    constexpr int THREADS = WM_ * WN_ * 32;
    constexpr int IM = TBM_ / WM_ / 16;
    constexpr int IN = TBM_ / WN_ / 8;
    constexpr int IP = IN / 2;
    constexpr int SZH = TBM_ * SROWH;              // halves per buffer
    static_assert(THREADS == 2 * TBM_, "loader mapping needs threads == 2*TBM");
    static_assert((IN & 1) == 0, "IN must be even");

    extern __shared__ __half smem[];
    __half* sA = smem;              // [2][SZH]
    __half* sB = smem + 2 * SZH;    // [2][SZH]

    const int tid  = threadIdx.x;
    const int wid  = tid >> 5;
    const int lane = tid & 31;
    const int g    = lane >> 2;
    const int tig  = lane & 3;
    const int bm = blockIdx.y * TBM_;
    const int bn = blockIdx.x * TBM_;
    const int wm = (wid % WM_) * (TBM_ / WM_);
    const int wn = (wid / WM_) * (TBM_ / WN_);
    const int lrow = tid >> 1;
    const int lcol = (tid & 1) * 16;               // halves offset (16 elems)

    const uint32_t sA_addr = (uint32_t)__cvta_generic_to_shared(sA);
    const uint32_t sB_addr = (uint32_t)__cvta_generic_to_shared(sB);
    // x4 mapping: lanes 0-15 -> rows (lane&15) at k0; lanes 16-31 -> same rows at k+8
    uint32_t a_base[IM], b_base[IP];
#pragma unroll
    for (int im = 0; im < IM; ++im)
        a_base[im] = sA_addr +
            (((wm + 16 * im + (lane & 15)) * SROWH + 8 * (lane >> 4)) << 1);
#pragma unroll
    for (int p = 0; p < IP; ++p)
        b_base[p] = sB_addr +
            (((wn + 16 * p + (lane & 15)) * SROWH + 8 * (lane >> 4)) << 1);

    float acc[IM][IN][4];
#pragma unroll
    for (int i = 0; i < IM; ++i)
#pragma unroll
        for (int j = 0; j < IN; ++j)
#pragma unroll
            for (int q = 0; q < 4; ++q) acc[i][j][q] = 0.f;

    const int nch0 = K0 / TBK, nch1 = K1 / TBK, nch2 = K2 / TBK;
    const int nch = nch0 + nch1 + nch2;

    float4 ra[4], rb[4];
    const float* Ap = A0; const float* Bp = B0; int Kk = K0; int k0 = 0;

    auto getc = [&](int c) {
        if (c < nch0)              { Ap = A0; Bp = B0;  Kk = K0; k0 = c * TBK; }
        else if (c < nch0 + nch1)  { Ap = A1; Bp = B1p; Kk = K1; k0 = (c - nch0) * TBK; }
        else                       { Ap = A2; Bp = B2p; Kk = K2; k0 = (c - nch0 - nch1) * TBK; }
    };
    auto ldg = [&]() {
        const float* ap = Ap + (size_t)(bm + lrow) * Kk + k0 + lcol;
        const float* bp = Bp + (size_t)(bn + lrow) * Kk + k0 + lcol;
#pragma unroll
        for (int q = 0; q < 4; ++q) { ra[q] = *(const float4*)(ap + 4 * q); }
#pragma unroll
        for (int q = 0; q < 4; ++q) { rb[q] = *(const float4*)(bp + 4 * q); }
    };
    auto sts = [&](int b) {
        __half* dA = sA + b * SZH + lrow * SROWH + lcol;
        __half* dB = sB + b * SZH + lrow * SROWH + lcol;
        uint4 pa = make_uint4(h2pack(ra[0].x, ra[0].y), h2pack(ra[0].z, ra[0].w),
                              h2pack(ra[1].x, ra[1].y), h2pack(ra[1].z, ra[1].w));
        uint4 pa2 = make_uint4(h2pack(ra[2].x, ra[2].y), h2pack(ra[2].z, ra[2].w),
                               h2pack(ra[3].x, ra[3].y), h2pack(ra[3].z, ra[3].w));
        uint4 pb = make_uint4(h2pack(rb[0].x, rb[0].y), h2pack(rb[0].z, rb[0].w),
                              h2pack(rb[1].x, rb[1].y), h2pack(rb[1].z, rb[1].w));
        uint4 pb2 = make_uint4(h2pack(rb[2].x, rb[2].y), h2pack(rb[2].z, rb[2].w),
                               h2pack(rb[3].x, rb[3].y), h2pack(rb[3].z, rb[3].w));
        *(uint4*)(dA)     = pa;
        *(uint4*)(dA + 8) = pa2;
        *(uint4*)(dB)     = pb;
        *(uint4*)(dB + 8) = pb2;
    };
    auto comp = [&](int b) {
        const uint32_t boff = (uint32_t)(b * SZH * 2);
#pragma unroll
        for (int k16 = 0; k16 < TBK; k16 += 16) {
            uint32_t afr[IM][4];
            uint32_t bfr[IN][2];
#pragma unroll
            for (int im = 0; im < IM; ++im)
                ldsm_x4(afr[im], a_base[im] + boff + (k16 << 1));
#pragma unroll
            for (int p = 0; p < IP; ++p) {
                uint32_t t[4];
                ldsm_x4(t, b_base[p] + boff + (k16 << 1));
                bfr[2 * p][0] = t[0]; bfr[2 * p + 1][0] = t[1];
                bfr[2 * p][1] = t[2]; bfr[2 * p + 1][1] = t[3];
            }
#pragma unroll
            for (int im = 0; im < IM; ++im)
#pragma unroll
                for (int in_ = 0; in_ < IN; ++in_)
                    mma_f16(acc[im][in_], afr[im], bfr[in_]);
        }
    };

    getc(0); ldg(); sts(0);
    __syncthreads();
    for (int c = 0; c < nch; ++c) {
        if (c + 1 < nch) { getc(c + 1); ldg(); }
        comp(c & 1);
        if (c + 1 < nch) { sts((c + 1) & 1); }
        __syncthreads();
    }

    // ---- epilogue with split output ----
#pragma unroll
    for (int im = 0; im < IM; ++im) {
#pragma unroll
        for (int in_ = 0; in_ < IN; ++in_) {
            int row0 = bm + wm + 16 * im + g;
            int col0 = bn + wn + 8 * in_ + 2 * tig;
            float c0 = acc[im][in_][0], c1 = acc[im][in_][1];
            float c2 = acc[im][in_][2], c3 = acc[im][in_][3];
            if (diagAdd != 0.f) {
                if (row0 == col0)         c0 += diagAdd;
                if (row0 == col0 + 1)     c1 += diagAdd;
                if (row0 + 8 == col0)     c2 += diagAdd;
                if (row0 + 8 == col0 + 1) c3 += diagAdd;
            }
            float* base; int st; int cc = col0;
            if (col0 >= NSPLIT) { base = C1; st = N1; cc = col0 - NSPLIT; }
            else                { base = C0; st = N0; }
            *(float2*)(base + (size_t)row0 * st + cc)       = make_float2(c0, c1);
            *(float2*)(base + (size_t)(row0 + 8) * st + cc) = make_float2(c2, c3);
        }
    }
}

// ---------------- frame elementwise builders ----------------
__global__ void build_MN_kernel(const float* __restrict__ S, const float* __restrict__ U)
{
    int idx = blockIdx.x * blockDim.x + threadIdx.x;
    if (idx < NXd * NXd) {
        int j = idx / NXd, n = idx - j * NXd;
        g_MmT[idx] = -0.5f * g_H[n * NXQ + j] - S[n * NXd + j] + S[j * NXd + n];
    } else if (idx < NXd * NXd + NQd * NXd) {
        int idx2 = idx - NXd * NXd;
        int j = idx2 / NXd, n = idx2 - j * NXd;
        g_NmT[idx2] = -(g_H[n * NXQ + NXd + j] + U[n * NQd + j]);
    } else {
        int k = idx - NXd * NXd - NQd * NXd;
        if (k < NQd) g_laminv[k] = 2.0f / g_H[(NXd + k) * NXQ + NXd + k];
    }
}

__global__ void build_DC_kernel(const float* __restrict__ U)
{
    int idx = blockIdx.x * blockDim.x + threadIdx.x;
    if (idx < NQd * NQd) {
        int j = idx / NQd, k = idx - j * NQd;
        g_D11T[idx] = (j < k) ? (-g_H[(NXd + k) * NXQ + NXd + j] * g_laminv[k]) : 0.f;
    } else {
        int idx2 = idx - NQd * NQd;
        if (idx2 < NQd * NXd) {
            int k = idx2 / NXd, i = idx2 - k * NXd;
            g_C1[idx2] = U[i * NQd + k] * g_laminv[k];
        }
    }
}

// ---------------- sequential triangular tanh solve ----------------
__global__ __launch_bounds__(256, 1) void solve_w_kernel()
{
    __shared__ float s_laminv[NQd];
    const int tid = threadIdx.x;
    s_laminv[tid] = g_laminv[tid];
    __syncthreads();

    const int c   = tid & 7;
    const int r   = tid >> 3;
    const int row = blockIdx.x * 32 + r;

    float acc[32];
    float wreg[32];

    const float* arow = g_a + row * NQd + c * 32;
#pragma unroll
    for (int i4 = 0; i4 < 8; ++i4) {
        float4 v = *(const float4*)(arow + 4 * i4);
        acc[4 * i4 + 0] = v.x; acc[4 * i4 + 1] = v.y;
        acc[4 * i4 + 2] = v.z; acc[4 * i4 + 3] = v.w;
    }

    for (int b = 0; b < 8; ++b) {
        const bool after = (c > b);
        const bool owner = (c == b);
#pragma unroll
        for (int jc = 0; jc < 32; ++jc) {
            const int j = (b << 5) + jc;
            float v  = acc[jc] * s_laminv[j];
            float ex = __expf(v + v);
            float wj = 1.f - __fdividef(2.f, ex + 1.f);
            wj = __shfl_sync(0xffffffffu, wj, b, 8);
            if (owner) wreg[jc] = wj;

            const float* drow = g_D11T + j * NQd + c * 32;
#pragma unroll
            for (int i4 = 0; i4 < 8; ++i4) {
                bool anyp = after || (owner && (4 * i4 + 3) > jc);
                float4 d = make_float4(0.f, 0.f, 0.f, 0.f);
                if (anyp) d = *(const float4*)(drow + 4 * i4);
                if (after || (owner && (4 * i4 + 0) > jc)) acc[4 * i4 + 0] = fmaf(wj, d.x, acc[4 * i4 + 0]);
                if (after || (owner && (4 * i4 + 1) > jc)) acc[4 * i4 + 1] = fmaf(wj, d.y, acc[4 * i4 + 1]);
                if (after || (owner && (4 * i4 + 2) > jc)) acc[4 * i4 + 2] = fmaf(wj, d.z, acc[4 * i4 + 2]);
                if (after || (owner && (4 * i4 + 3) > jc)) acc[4 * i4 + 3] = fmaf(wj, d.w, acc[4 * i4 + 3]);
            }
        }
    }

    float* wrow = g_w + row * NQd + c * 32;
#pragma unroll
    for (int i4 = 0; i4 < 8; ++i4) {
        *(float4*)(wrow + 4 * i4) =
            make_float4(wreg[4 * i4 + 0], wreg[4 * i4 + 1], wreg[4 * i4 + 2], wreg[4 * i4 + 3]);
    }
}

// ---------------- launch ----------------
extern "C" void kernel_launch(void* const* d_in, const int* in_sizes, int n_in,
                              void* d_out, int out_size)
{
    const float* u_in  = (const float*)d_in[0];
    const float* x_in  = (const float*)d_in[1];
    const float* X_in  = (const float*)d_in[2];
    const float* S_in  = (const float*)d_in[3];
    const float* Pv_in = (const float*)d_in[4];
    const float* U_in  = (const float*)d_in[5];
    const float* D12   = (const float*)d_in[6];
    const float* B2    = (const float*)d_in[7];
    const float* C2    = (const float*)d_in[8];
    const float* D21   = (const float*)d_in[9];
    const float* D22   = (const float*)d_in[10];

    float* out = (float*)d_out;
    float* dx  = out;
    float* y   = out + (size_t)NBd * NXd;

    float *H, *Pi, *MmT, *NmT, *C1, *BB0, *BB1, *BB2, *a, *w;
    cudaGetSymbolAddress((void**)&H,   g_H);
    cudaGetSymbolAddress((void**)&Pi,  g_Pi);
    cudaGetSymbolAddress((void**)&MmT, g_MmT);
    cudaGetSymbolAddress((void**)&NmT, g_NmT);
    cudaGetSymbolAddress((void**)&C1,  g_C1);
    cudaGetSymbolAddress((void**)&BB0, g_BigB0);
    cudaGetSymbolAddress((void**)&BB1, g_BigB1);
    cudaGetSymbolAddress((void**)&BB2, g_BigB2);
    cudaGetSymbolAddress((void**)&a,   g_a);
    cudaGetSymbolAddress((void**)&w,   g_w);

    auto Big   = gemm_tc_t<128, 2, 4>;
    auto Small = gemm_tc_t<64, 2, 2>;
    const int SMEM_BIG   = 4 * 128 * SROWH * 2;   // 40960 B
    const int SMEM_SMALL = 4 * 64 * SROWH * 2;    // 20480 B
    cudaFuncSetAttribute(Big,   cudaFuncAttributeMaxDynamicSharedMemorySize, SMEM_BIG);
    cudaFuncSetAttribute(Small, cudaFuncAttributeMaxDynamicSharedMemorySize, SMEM_SMALL);

    const int NOSPLIT = 1 << 30;

    // (1) H = X X^T + eps I   (768x768, K=768)
    Small<<<dim3(NXQ / 64, NXQ / 64), 128, SMEM_SMALL>>>(
        X_in, X_in, NXQ, nullptr, nullptr, 0, nullptr, nullptr, 0,
        H, NXQ, nullptr, 0, NOSPLIT, EPS_C);

    // (2) MmT, NmT, laminv
    build_MN_kernel<<<(NXd * NXd + NQd * NXd + NQd + 255) / 256, 256>>>(S_in, U_in);

    // (3) D11T, C1
    build_DC_kernel<<<(NQd * NQd + NQd * NXd + 255) / 256, 256>>>(U_in);

    // (4) a = x C1^T + u D12^T  (4096x256)  <-- ncu-profiled slot
    Small<<<dim3(NQd / 64, NBd / 64), 128, SMEM_SMALL>>>(
        x_in, C1, NXd, u_in, D12, NQd, nullptr, nullptr, 0,
        a, NQd, nullptr, 0, NOSPLIT, 0.f);

    // (5) Pi = P_inv P_inv^T  (512x512)
    Small<<<dim3(NXd / 64, NXd / 64), 128, SMEM_SMALL>>>(
        Pv_in, Pv_in, NXd, nullptr, nullptr, 0, nullptr, nullptr, 0,
        Pi, NXd, nullptr, 0, NOSPLIT, 0.f);

    // (6) A = Pi @ M - alpha I  -> BigB0 rows 0..511
    Small<<<dim3(NXd / 64, NXd / 64), 128, SMEM_SMALL>>>(
        Pi, MmT, NXd, nullptr, nullptr, 0, nullptr, nullptr, 0,
        BB0, NXd, nullptr, 0, NOSPLIT, -ALPHA_C);

    // (7) B1 = Pi @ N  -> BigB1 rows 0..511
    Small<<<dim3(NQd / 64, NXd / 64), 128, SMEM_SMALL>>>(
        Pi, NmT, NXd, nullptr, nullptr, 0, nullptr, nullptr, 0,
        BB1, NQd, nullptr, 0, NOSPLIT, 0.f);

    // concat tails: [A;C2], [B1;D21], [B2;D22]
    cudaMemcpyAsync(BB0 + (size_t)NXd * NXd, C2,  (size_t)NYd * NXd * 4, cudaMemcpyDeviceToDevice);
    cudaMemcpyAsync(BB1 + (size_t)NXd * NQd, D21, (size_t)NYd * NQd * 4, cudaMemcpyDeviceToDevice);
    cudaMemcpyAsync(BB2,                     B2,  (size_t)NXd * NUd * 4, cudaMemcpyDeviceToDevice);
    cudaMemcpyAsync(BB2 + (size_t)NXd * NUd, D22, (size_t)NYd * NUd * 4, cudaMemcpyDeviceToDevice);

    // (8) sequential tanh solve -> w
    solve_w_kernel<<<NBd / 32, 256>>>();

    // (9) [dx | y] = x [A;C2]^T + w [B1;D21]^T + u [B2;D22]^T  (4096x768)
    Big<<<dim3((NXd + NYd) / 128, NBd / 128), 256, SMEM_BIG>>>(
        x_in, BB0, NXd, w, BB1, NQd, u_in, BB2, NUd,
        dx, NXd, y, NYd, NXd, 0.f);

    (void)in_sizes; (void)n_in; (void)out_size;
}

// round 7
// speedup vs baseline: 1.9889x; 1.0006x over previous
#include <cuda_runtime.h>
#include <cuda_fp16.h>
#include <cstdint>
#include <math.h>

#define ALPHA_C 0.5f
#define EPS_C   0.01f
#define NBd 4096
#define NXd 512
#define NYd 256
#define NUd 256
#define NQd 256
#define NXQ 768

#define TBK 32
#define SROWH 40   // smem row stride in halves (80B): LDSM conflict-free

// ---------------- device scratch ----------------
__device__ float g_H[NXQ * NXQ];
__device__ float g_Pi[NXd * NXd];
__device__ float g_MmT[NXd * NXd];
__device__ float g_NmT[NQd * NXd];
__device__ float g_laminv[NQd];
__device__ float g_D11T[NQd * NQd];
__device__ float g_C1[NQd * NXd];
__device__ float g_BigB0[(NXd + NYd) * NXd];   // [A ; C2]   768 x 512
__device__ float g_BigB1[(NXd + NYd) * NQd];   // [B1 ; D21] 768 x 256
__device__ float g_BigB2[(NXd + NYd) * NUd];   // [B2 ; D22] 768 x 256
__device__ float g_a[NBd * NQd];
__device__ float g_w[NBd * NQd];

__device__ __forceinline__ void mma_f16(float c[4], const uint32_t a[4], const uint32_t b[2]) {
    asm volatile(
        "mma.sync.aligned.m16n8k16.row.col.f32.f16.f16.f32 "
        "{%0,%1,%2,%3}, {%4,%5,%6,%7}, {%8,%9}, {%0,%1,%2,%3};"
        : "+f"(c[0]), "+f"(c[1]), "+f"(c[2]), "+f"(c[3])
        : "r"(a[0]), "r"(a[1]), "r"(a[2]), "r"(a[3]), "r"(b[0]), "r"(b[1]));
}
__device__ __forceinline__ void ldsm_x4(uint32_t r[4], uint32_t addr) {
    asm volatile("ldmatrix.sync.aligned.m8n8.x4.shared.b16 {%0,%1,%2,%3}, [%4];"
        : "=r"(r[0]), "=r"(r[1]), "=r"(r[2]), "=r"(r[3]) : "r"(addr));
}
__device__ __forceinline__ uint32_t h2pack(float lo, float hi) {
    __half2 h = __floats2half2_rn(lo, hi);
    return *(uint32_t*)&h;
}

// ---------------- pipelined fp16 mma.sync NT GEMM (template) ----------------
// C = sum_seg Aseg[M][Ks] @ Bseg[N][Ks]^T  (+ diagAdd on i==j)
// fp32 gmem -> half smem (double-buffered), m16n8k16 fp16 MMA, fp32 accum.
template<int TBM_, int WM_, int WN_>
__global__ void __launch_bounds__(WM_ * WN_ * 32) gemm_tc_t(
    const float* __restrict__ A0, const float* __restrict__ B0, int K0,
    const float* __restrict__ A1, const float* __restrict__ B1p, int K1,
    const float* __restrict__ A2, const float* __restrict__ B2p, int K2,
    float* __restrict__ C0, int N0, float* __restrict__ C1, int N1, int NSPLIT,
    float diagAdd)
{
    constexpr int THREADS = WM_ * WN_ * 32;
    constexpr int IM = TBM_ / WM_ / 16;
    constexpr int IN = TBM_ / WN_ / 8;
    constexpr int IP = IN / 2;
    constexpr int SZH = TBM_ * SROWH;              // halves per buffer
    static_assert(THREADS == 2 * TBM_, "loader mapping needs threads == 2*TBM");
    static_assert((IN & 1) == 0, "IN must be even");

    extern __shared__ __half smem[];
    __half* sA = smem;              // [2][SZH]
    __half* sB = smem + 2 * SZH;    // [2][SZH]

    const int tid  = threadIdx.x;
    const int wid  = tid >> 5;
    const int lane = tid & 31;
    const int g    = lane >> 2;
    const int tig  = lane & 3;
    const int bm = blockIdx.y * TBM_;
    const int bn = blockIdx.x * TBM_;
    const int wm = (wid % WM_) * (TBM_ / WM_);
    const int wn = (wid / WM_) * (TBM_ / WN_);
    const int lrow = tid >> 1;
    const int lcol = (tid & 1) * 16;               // halves offset (16 elems)

    const uint32_t sA_addr = (uint32_t)__cvta_generic_to_shared(sA);
    const uint32_t sB_addr = (uint32_t)__cvta_generic_to_shared(sB);
    // x4 mapping: lanes 0-15 -> rows (lane&15) at k0; lanes 16-31 -> same rows at k+8
    uint32_t a_base[IM], b_base[IP];
#pragma unroll
    for (int im = 0; im < IM; ++im)
        a_base[im] = sA_addr +
            (((wm + 16 * im + (lane & 15)) * SROWH + 8 * (lane >> 4)) << 1);
#pragma unroll
    for (int p = 0; p < IP; ++p)
        b_base[p] = sB_addr +
            (((wn + 16 * p + (lane & 15)) * SROWH + 8 * (lane >> 4)) << 1);

    float acc[IM][IN][4];
#pragma unroll
    for (int i = 0; i < IM; ++i)
#pragma unroll
        for (int j = 0; j < IN; ++j)
#pragma unroll
            for (int q = 0; q < 4; ++q) acc[i][j][q] = 0.f;

    const int nch0 = K0 / TBK, nch1 = K1 / TBK, nch2 = K2 / TBK;
    const int nch = nch0 + nch1 + nch2;

    float4 ra[4], rb[4];
    const float* Ap = A0; const float* Bp = B0; int Kk = K0; int k0 = 0;

    auto getc = [&](int c) {
        if (c < nch0)              { Ap = A0; Bp = B0;  Kk = K0; k0 = c * TBK; }
        else if (c < nch0 + nch1)  { Ap = A1; Bp = B1p; Kk = K1; k0 = (c - nch0) * TBK; }
        else                       { Ap = A2; Bp = B2p; Kk = K2; k0 = (c - nch0 - nch1) * TBK; }
    };
    auto ldg = [&]() {
        const float* ap = Ap + (size_t)(bm + lrow) * Kk + k0 + lcol;
        const float* bp = Bp + (size_t)(bn + lrow) * Kk + k0 + lcol;
#pragma unroll
        for (int q = 0; q < 4; ++q) { ra[q] = *(const float4*)(ap + 4 * q); }
#pragma unroll
        for (int q = 0; q < 4; ++q) { rb[q] = *(const float4*)(bp + 4 * q); }
    };
    auto sts = [&](int b) {
        __half* dA = sA + b * SZH + lrow * SROWH + lcol;
        __half* dB = sB + b * SZH + lrow * SROWH + lcol;
        uint4 pa = make_uint4(h2pack(ra[0].x, ra[0].y), h2pack(ra[0].z, ra[0].w),
                              h2pack(ra[1].x, ra[1].y), h2pack(ra[1].z, ra[1].w));
        uint4 pa2 = make_uint4(h2pack(ra[2].x, ra[2].y), h2pack(ra[2].z, ra[2].w),
                               h2pack(ra[3].x, ra[3].y), h2pack(ra[3].z, ra[3].w));
        uint4 pb = make_uint4(h2pack(rb[0].x, rb[0].y), h2pack(rb[0].z, rb[0].w),
                              h2pack(rb[1].x, rb[1].y), h2pack(rb[1].z, rb[1].w));
        uint4 pb2 = make_uint4(h2pack(rb[2].x, rb[2].y), h2pack(rb[2].z, rb[2].w),
                               h2pack(rb[3].x, rb[3].y), h2pack(rb[3].z, rb[3].w));
        *(uint4*)(dA)     = pa;
        *(uint4*)(dA + 8) = pa2;
        *(uint4*)(dB)     = pb;
        *(uint4*)(dB + 8) = pb2;
    };
    auto comp = [&](int b) {
        const uint32_t boff = (uint32_t)(b * SZH * 2);
#pragma unroll
        for (int k16 = 0; k16 < TBK; k16 += 16) {
            uint32_t afr[IM][4];
            uint32_t bfr[IN][2];
#pragma unroll
            for (int im = 0; im < IM; ++im)
                ldsm_x4(afr[im], a_base[im] + boff + (k16 << 1));
#pragma unroll
            for (int p = 0; p < IP; ++p) {
                uint32_t t[4];
                ldsm_x4(t, b_base[p] + boff + (k16 << 1));
                bfr[2 * p][0] = t[0]; bfr[2 * p + 1][0] = t[1];
                bfr[2 * p][1] = t[2]; bfr[2 * p + 1][1] = t[3];
            }
#pragma unroll
            for (int im = 0; im < IM; ++im)
#pragma unroll
                for (int in_ = 0; in_ < IN; ++in_)
                    mma_f16(acc[im][in_], afr[im], bfr[in_]);
        }
    };

    getc(0); ldg(); sts(0);
    __syncthreads();
    for (int c = 0; c < nch; ++c) {
        if (c + 1 < nch) { getc(c + 1); ldg(); }
        comp(c & 1);
        if (c + 1 < nch) { sts((c + 1) & 1); }
        __syncthreads();
    }

    // ---- epilogue with split output ----
#pragma unroll
    for (int im = 0; im < IM; ++im) {
#pragma unroll
        for (int in_ = 0; in_ < IN; ++in_) {
            int row0 = bm + wm + 16 * im + g;
            int col0 = bn + wn + 8 * in_ + 2 * tig;
            float c0 = acc[im][in_][0], c1 = acc[im][in_][1];
            float c2 = acc[im][in_][2], c3 = acc[im][in_][3];
            if (diagAdd != 0.f) {
                if (row0 == col0)         c0 += diagAdd;
                if (row0 == col0 + 1)     c1 += diagAdd;
                if (row0 + 8 == col0)     c2 += diagAdd;
                if (row0 + 8 == col0 + 1) c3 += diagAdd;
            }
            float* base; int st; int cc = col0;
            if (col0 >= NSPLIT) { base = C1; st = N1; cc = col0 - NSPLIT; }
            else                { base = C0; st = N0; }
            *(float2*)(base + (size_t)row0 * st + cc)       = make_float2(c0, c1);
            *(float2*)(base + (size_t)(row0 + 8) * st + cc) = make_float2(c2, c3);
        }
    }
}

// ---------------- frame elementwise builders ----------------
__global__ void build_MN_kernel(const float* __restrict__ S, const float* __restrict__ U)
{
    int idx = blockIdx.x * blockDim.x + threadIdx.x;
    if (idx < NXd * NXd) {
        int j = idx / NXd, n = idx - j * NXd;
        g_MmT[idx] = -0.5f * g_H[n * NXQ + j] - S[n * NXd + j] + S[j * NXd + n];
    } else if (idx < NXd * NXd + NQd * NXd) {
        int idx2 = idx - NXd * NXd;
        int j = idx2 / NXd, n = idx2 - j * NXd;
        g_NmT[idx2] = -(g_H[n * NXQ + NXd + j] + U[n * NQd + j]);
    } else {
        int k = idx - NXd * NXd - NQd * NXd;
        if (k < NQd) g_laminv[k] = 2.0f / g_H[(NXd + k) * NXQ + NXd + k];
    }
}

__global__ void build_DC_kernel(const float* __restrict__ U)
{
    int idx = blockIdx.x * blockDim.x + threadIdx.x;
    if (idx < NQd * NQd) {
        int j = idx / NQd, k = idx - j * NQd;
        g_D11T[idx] = (j < k) ? (-g_H[(NXd + k) * NXQ + NXd + j] * g_laminv[k]) : 0.f;
    } else {
        int idx2 = idx - NQd * NQd;
        if (idx2 < NQd * NXd) {
            int k = idx2 / NXd, i = idx2 - k * NXd;
            g_C1[idx2] = U[i * NQd + k] * g_laminv[k];
        }
    }
}

// ---------------- sequential triangular tanh solve ----------------
__global__ __launch_bounds__(256, 1) void solve_w_kernel()
{
    __shared__ float s_laminv[NQd];
    const int tid = threadIdx.x;
    s_laminv[tid] = g_laminv[tid];
    __syncthreads();

    const int c   = tid & 7;
    const int r   = tid >> 3;
    const int row = blockIdx.x * 32 + r;

    float acc[32];
    float wreg[32];

    const float* arow = g_a + row * NQd + c * 32;
#pragma unroll
    for (int i4 = 0; i4 < 8; ++i4) {
        float4 v = *(const float4*)(arow + 4 * i4);
        acc[4 * i4 + 0] = v.x; acc[4 * i4 + 1] = v.y;
        acc[4 * i4 + 2] = v.z; acc[4 * i4 + 3] = v.w;
    }

    for (int b = 0; b < 8; ++b) {
        const bool after = (c > b);
        const bool owner = (c == b);
#pragma unroll
        for (int jc = 0; jc < 32; ++jc) {
            const int j = (b << 5) + jc;
            float v  = acc[jc] * s_laminv[j];
            float ex = __expf(v + v);
            float wj = 1.f - __fdividef(2.f, ex + 1.f);
            wj = __shfl_sync(0xffffffffu, wj, b, 8);
            if (owner) wreg[jc] = wj;

            const float* drow = g_D11T + j * NQd + c * 32;
#pragma unroll
            for (int i4 = 0; i4 < 8; ++i4) {
                bool anyp = after || (owner && (4 * i4 + 3) > jc);
                float4 d = make_float4(0.f, 0.f, 0.f, 0.f);
                if (anyp) d = *(const float4*)(drow + 4 * i4);
                if (after || (owner && (4 * i4 + 0) > jc)) acc[4 * i4 + 0] = fmaf(wj, d.x, acc[4 * i4 + 0]);
                if (after || (owner && (4 * i4 + 1) > jc)) acc[4 * i4 + 1] = fmaf(wj, d.y, acc[4 * i4 + 1]);
                if (after || (owner && (4 * i4 + 2) > jc)) acc[4 * i4 + 2] = fmaf(wj, d.z, acc[4 * i4 + 2]);
                if (after || (owner && (4 * i4 + 3) > jc)) acc[4 * i4 + 3] = fmaf(wj, d.w, acc[4 * i4 + 3]);
            }
        }
    }

    float* wrow = g_w + row * NQd + c * 32;
#pragma unroll
    for (int i4 = 0; i4 < 8; ++i4) {
        *(float4*)(wrow + 4 * i4) =
            make_float4(wreg[4 * i4 + 0], wreg[4 * i4 + 1], wreg[4 * i4 + 2], wreg[4 * i4 + 3]);
    }
}

// ---------------- launch ----------------
extern "C" void kernel_launch(void* const* d_in, const int* in_sizes, int n_in,
                              void* d_out, int out_size)
{
    const float* u_in  = (const float*)d_in[0];
    const float* x_in  = (const float*)d_in[1];
    const float* X_in  = (const float*)d_in[2];
    const float* S_in  = (const float*)d_in[3];
    const float* Pv_in = (const float*)d_in[4];
    const float* U_in  = (const float*)d_in[5];
    const float* D12   = (const float*)d_in[6];
    const float* B2    = (const float*)d_in[7];
    const float* C2    = (const float*)d_in[8];
    const float* D21   = (const float*)d_in[9];
    const float* D22   = (const float*)d_in[10];

    float* out = (float*)d_out;
    float* dx  = out;
    float* y   = out + (size_t)NBd * NXd;

    float *H, *Pi, *MmT, *NmT, *C1, *BB0, *BB1, *BB2, *a, *w;
    cudaGetSymbolAddress((void**)&H,   g_H);
    cudaGetSymbolAddress((void**)&Pi,  g_Pi);
    cudaGetSymbolAddress((void**)&MmT, g_MmT);
    cudaGetSymbolAddress((void**)&NmT, g_NmT);
    cudaGetSymbolAddress((void**)&C1,  g_C1);
    cudaGetSymbolAddress((void**)&BB0, g_BigB0);
    cudaGetSymbolAddress((void**)&BB1, g_BigB1);
    cudaGetSymbolAddress((void**)&BB2, g_BigB2);
    cudaGetSymbolAddress((void**)&a,   g_a);
    cudaGetSymbolAddress((void**)&w,   g_w);

    auto Big   = gemm_tc_t<128, 2, 4>;
    auto Small = gemm_tc_t<64, 2, 2>;
    const int SMEM_BIG   = 4 * 128 * SROWH * 2;   // 40960 B
    const int SMEM_SMALL = 4 * 64 * SROWH * 2;    // 20480 B
    cudaFuncSetAttribute(Big,   cudaFuncAttributeMaxDynamicSharedMemorySize, SMEM_BIG);
    cudaFuncSetAttribute(Small, cudaFuncAttributeMaxDynamicSharedMemorySize, SMEM_SMALL);

    const int NOSPLIT = 1 << 30;

    // (1) H = X X^T + eps I   (768x768, K=768)
    Small<<<dim3(NXQ / 64, NXQ / 64), 128, SMEM_SMALL>>>(
        X_in, X_in, NXQ, nullptr, nullptr, 0, nullptr, nullptr, 0,
        H, NXQ, nullptr, 0, NOSPLIT, EPS_C);

    // (2) MmT, NmT, laminv
    build_MN_kernel<<<(NXd * NXd + NQd * NXd + NQd + 255) / 256, 256>>>(S_in, U_in);

    // (3) D11T, C1
    build_DC_kernel<<<(NQd * NQd + NQd * NXd + 255) / 256, 256>>>(U_in);

    // (4) a = x C1^T + u D12^T  (4096x256)  <-- ncu-profiled slot
    Small<<<dim3(NQd / 64, NBd / 64), 128, SMEM_SMALL>>>(
        x_in, C1, NXd, u_in, D12, NQd, nullptr, nullptr, 0,
        a, NQd, nullptr, 0, NOSPLIT, 0.f);

    // (5) Pi = P_inv P_inv^T  (512x512)
    Small<<<dim3(NXd / 64, NXd / 64), 128, SMEM_SMALL>>>(
        Pv_in, Pv_in, NXd, nullptr, nullptr, 0, nullptr, nullptr, 0,
        Pi, NXd, nullptr, 0, NOSPLIT, 0.f);

    // (6) A = Pi @ M - alpha I  -> BigB0 rows 0..511
    Small<<<dim3(NXd / 64, NXd / 64), 128, SMEM_SMALL>>>(
        Pi, MmT, NXd, nullptr, nullptr, 0, nullptr, nullptr, 0,
        BB0, NXd, nullptr, 0, NOSPLIT, -ALPHA_C);

    // (7) B1 = Pi @ N  -> BigB1 rows 0..511
    Small<<<dim3(NQd / 64, NXd / 64), 128, SMEM_SMALL>>>(
        Pi, NmT, NXd, nullptr, nullptr, 0, nullptr, nullptr, 0,
        BB1, NQd, nullptr, 0, NOSPLIT, 0.f);

    // concat tails: [A;C2], [B1;D21], [B2;D22]
    cudaMemcpyAsync(BB0 + (size_t)NXd * NXd, C2,  (size_t)NYd * NXd * 4, cudaMemcpyDeviceToDevice);
    cudaMemcpyAsync(BB1 + (size_t)NXd * NQd, D21, (size_t)NYd * NQd * 4, cudaMemcpyDeviceToDevice);
    cudaMemcpyAsync(BB2,                     B2,  (size_t)NXd * NUd * 4, cudaMemcpyDeviceToDevice);
    cudaMemcpyAsync(BB2 + (size_t)NXd * NUd, D22, (size_t)NYd * NUd * 4, cudaMemcpyDeviceToDevice);

    // (8) sequential tanh solve -> w
    solve_w_kernel<<<NBd / 32, 256>>>();

    // (9) [dx | y] = x [A;C2]^T + w [B1;D21]^T + u [B2;D22]^T  (4096x768)
    Big<<<dim3((NXd + NYd) / 128, NBd / 128), 256, SMEM_BIG>>>(
        x_in, BB0, NXd, w, BB1, NQd, u_in, BB2, NUd,
        dx, NXd, y, NYd, NXd, 0.f);

    (void)in_sizes; (void)n_in; (void)out_size;
}